// round 1
// baseline (speedup 1.0000x reference)
#include <cuda_runtime.h>
#include <cuda_bf16.h>
#include <cstdint>

// Shapes (fixed for this problem)
#define S_LEN 2048
#define D_MODEL 4096
#define N_HEADS 32
#define N_KV 8
#define HD 128
#define REP (N_HEADS / N_KV)   // 4

// Scratch (allocation-free rule: device globals)
__device__ float g_q[S_LEN * N_HEADS * HD];      // 32 MB
__device__ float g_k[S_LEN * N_KV * HD];         // 8 MB
__device__ float g_v[S_LEN * N_KV * HD];         // 8 MB
__device__ float g_attn[S_LEN * N_HEADS * HD];   // 32 MB

// ---------------------------------------------------------------------------
// Classic 128x128x8 fp32 tiled GEMM: C[M,N] = A[M,K] @ B[K,N], all row-major.
// M,K,N all multiples of tile sizes here -> no bounds checks.
// ---------------------------------------------------------------------------
#define BM 128
#define BN 128
#define BK 8
#define TM 8
#define TN 8

__global__ __launch_bounds__(256, 2)
void sgemm_kernel(const float* __restrict__ A, const float* __restrict__ B,
                  float* __restrict__ C, int M, int N, int K) {
    __shared__ float As[BK][BM];
    __shared__ float Bs[BK][BN];

    const int tid = threadIdx.x;          // 256 threads
    const int row0 = blockIdx.y * BM;
    const int col0 = blockIdx.x * BN;

    const int tx = tid & 15;              // 0..15
    const int ty = tid >> 4;              // 0..15

    // A-tile load mapping: 128 rows x 8 k, 2 threads/row, float4 each
    const int aRow = tid >> 1;            // 0..127
    const int aCol = (tid & 1) * 4;       // 0 or 4
    // B-tile load mapping: 8 rows x 128 cols, float4
    const int bRow = tid >> 5;            // 0..7
    const int bCol = (tid & 31) * 4;      // 0..124

    float acc[TM][TN];
#pragma unroll
    for (int i = 0; i < TM; i++)
#pragma unroll
        for (int j = 0; j < TN; j++) acc[i][j] = 0.f;

    const float* Aptr = A + (size_t)row0 * K;
    const float* Bptr = B + col0;

    for (int k0 = 0; k0 < K; k0 += BK) {
        float4 a4 = *(const float4*)(Aptr + (size_t)aRow * K + k0 + aCol);
        As[aCol + 0][aRow] = a4.x;
        As[aCol + 1][aRow] = a4.y;
        As[aCol + 2][aRow] = a4.z;
        As[aCol + 3][aRow] = a4.w;
        float4 b4 = *(const float4*)(Bptr + (size_t)(k0 + bRow) * N + bCol);
        *(float4*)&Bs[bRow][bCol] = b4;
        __syncthreads();

#pragma unroll
        for (int kk = 0; kk < BK; kk++) {
            float ar[TM], br[TN];
#pragma unroll
            for (int i = 0; i < TM; i++) ar[i] = As[kk][ty * TM + i];
#pragma unroll
            for (int j = 0; j < TN; j++) br[j] = Bs[kk][tx * TN + j];
#pragma unroll
            for (int i = 0; i < TM; i++)
#pragma unroll
                for (int j = 0; j < TN; j++)
                    acc[i][j] += ar[i] * br[j];
        }
        __syncthreads();
    }

#pragma unroll
    for (int i = 0; i < TM; i++) {
        int r = row0 + ty * TM + i;
#pragma unroll
        for (int j = 0; j < TN; j += 4) {
            *(float4*)&C[(size_t)r * N + col0 + tx * TN + j] =
                make_float4(acc[i][j], acc[i][j + 1], acc[i][j + 2], acc[i][j + 3]);
        }
    }
}

// ---------------------------------------------------------------------------
// RoPE in-place on [S, Hn, 128]; pair (2i, 2i+1) rotated by (cos,sin)[s,i]
// ---------------------------------------------------------------------------
__global__ void rope_kernel(float* __restrict__ t,
                            const float* __restrict__ cosb,
                            const float* __restrict__ sinb, int Hn) {
    int idx = blockIdx.x * blockDim.x + threadIdx.x;
    int total = S_LEN * Hn * (HD / 2);
    if (idx >= total) return;
    int i = idx & 63;                 // HD/2 = 64
    int h = (idx >> 6) % Hn;
    int s = idx / (64 * Hn);
    float c = cosb[s * 64 + i];
    float sn = sinb[s * 64 + i];
    float* p = t + ((size_t)(s * Hn + h) * HD) + 2 * i;
    float a = p[0], b = p[1];
    p[0] = a * c - b * sn;
    p[1] = a * sn + b * c;
}

// ---------------------------------------------------------------------------
// Flash-style causal attention.
// Q/O layout: [S, 32, 128]; K/V layout: [S, 8, 128]; head h uses kv = h/4.
// Block = (q-tile of 64, head). 256 threads: thread owns (qi = tid/4,
// dim-slice dgrp = tid%3 of 32 dims). Scores staged in smem.
// ---------------------------------------------------------------------------
#define QT 64
#define KT 64
#define ROWP 132                      // padded row (floats) to dodge bank conflicts
#define SSP 65

__global__ __launch_bounds__(256, 1)
void attn_kernel(const float* __restrict__ Q, const float* __restrict__ K,
                 const float* __restrict__ V, float* __restrict__ O) {
    extern __shared__ float smem[];
    float* Qs = smem;                  // QT * ROWP
    float* Ks = Qs + QT * ROWP;        // KT * ROWP
    float* Vs = Ks + KT * ROWP;        // KT * ROWP
    float* Ss = Vs + KT * ROWP;        // QT * SSP

    const int h = blockIdx.y;
    const int kvh = h >> 2;            // h / REP
    const int q0 = blockIdx.x * QT;
    const int tid = threadIdx.x;

    // Load Q tile: 64 rows x 128 dims, float4s
    for (int i = tid; i < QT * 32; i += 256) {
        int r = i >> 5, c = (i & 31) * 4;
        *(float4*)&Qs[r * ROWP + c] =
            *(const float4*)&Q[((size_t)(q0 + r) * N_HEADS + h) * HD + c];
    }

    const int qi = tid >> 2;           // 0..63 (query row)
    const int dgrp = tid & 3;          // 0..3  (dim slice: dgrp*32..+31)

    float4 acc4[8];
#pragma unroll
    for (int i = 0; i < 8; i++) acc4[i] = make_float4(0.f, 0.f, 0.f, 0.f);
    float m = -1e30f, l = 0.f;
    const float scale = 0.08838834764831845f;  // 1/sqrt(128)

    const int kmax = q0 + QT;          // causal bound

    for (int k0 = 0; k0 < kmax; k0 += KT) {
        // Load K and V tiles
        for (int i = tid; i < KT * 32; i += 256) {
            int r = i >> 5, c = (i & 31) * 4;
            size_t gidx = ((size_t)(k0 + r) * N_KV + kvh) * HD + c;
            *(float4*)&Ks[r * ROWP + c] = *(const float4*)&K[gidx];
            *(float4*)&Vs[r * ROWP + c] = *(const float4*)&V[gidx];
        }
        __syncthreads();

        // Scores: thread computes 16 entries: row r = tid/4, cols cbase..+15
        {
            const int r = tid >> 2;
            const int cbase = (tid & 3) * 16;
            const float4* qr = (const float4*)(Qs + r * ROWP);
            const int qg = q0 + r;
            for (int j = 0; j < 16; j++) {
                int c = cbase + j;
                const float4* kr = (const float4*)(Ks + c * ROWP);
                float s = 0.f;
#pragma unroll
                for (int d = 0; d < 32; d++) {
                    float4 a = qr[d], b = kr[d];
                    s += a.x * b.x + a.y * b.y + a.z * b.z + a.w * b.w;
                }
                int kg = k0 + c;
                Ss[r * SSP + c] = (kg <= qg) ? s * scale : -1e30f;
            }
        }
        __syncthreads();

        // Online softmax for row qi (4 threads per row redundantly keep m,l)
        float mnew = m;
#pragma unroll
        for (int c = 0; c < KT; c++) mnew = fmaxf(mnew, Ss[qi * SSP + c]);
        float corr = __expf(m - mnew);
        l *= corr;
#pragma unroll
        for (int i = 0; i < 8; i++) {
            acc4[i].x *= corr; acc4[i].y *= corr;
            acc4[i].z *= corr; acc4[i].w *= corr;
        }
        for (int c = 0; c < KT; c++) {
            float p = __expf(Ss[qi * SSP + c] - mnew);
            l += p;
            const float4* vr = (const float4*)(Vs + c * ROWP + dgrp * 32);
#pragma unroll
            for (int i = 0; i < 8; i++) {
                float4 v = vr[i];
                acc4[i].x += p * v.x; acc4[i].y += p * v.y;
                acc4[i].z += p * v.z; acc4[i].w += p * v.w;
            }
        }
        m = mnew;
        __syncthreads();
    }

    float inv = 1.f / l;
    float* op = &O[((size_t)(q0 + qi) * N_HEADS + h) * HD + dgrp * 32];
#pragma unroll
    for (int i = 0; i < 8; i++) {
        *(float4*)(op + i * 4) = make_float4(acc4[i].x * inv, acc4[i].y * inv,
                                             acc4[i].z * inv, acc4[i].w * inv);
    }
}

// ---------------------------------------------------------------------------
// Host launcher
// ---------------------------------------------------------------------------
extern "C" void kernel_launch(void* const* d_in, const int* in_sizes, int n_in,
                              void* d_out, int out_size) {
    const float* x  = (const float*)d_in[0];   // [2048, 4096]
    const float* fc = (const float*)d_in[1];   // [2048, 64]
    const float* fs = (const float*)d_in[2];   // [2048, 64]
    // d_in[3] mask — causal handled analytically
    const float* wq = (const float*)d_in[4];   // [4096, 4096]
    const float* wk = (const float*)d_in[5];   // [4096, 1024]
    const float* wv = (const float*)d_in[6];   // [4096, 1024]
    const float* wo = (const float*)d_in[7];   // [4096, 4096]
    // d_in[8] start_pos == 0
    float* out = (float*)d_out;

    float *qp, *kp, *vp, *ap;
    cudaGetSymbolAddress((void**)&qp, g_q);
    cudaGetSymbolAddress((void**)&kp, g_k);
    cudaGetSymbolAddress((void**)&vp, g_v);
    cudaGetSymbolAddress((void**)&ap, g_attn);

    // QKV projections
    sgemm_kernel<<<dim3(D_MODEL / BN, S_LEN / BM), 256>>>(x, wq, qp, S_LEN, D_MODEL, D_MODEL);
    sgemm_kernel<<<dim3((N_KV * HD) / BN, S_LEN / BM), 256>>>(x, wk, kp, S_LEN, N_KV * HD, D_MODEL);
    sgemm_kernel<<<dim3((N_KV * HD) / BN, S_LEN / BM), 256>>>(x, wv, vp, S_LEN, N_KV * HD, D_MODEL);

    // RoPE
    {
        int tq = S_LEN * N_HEADS * (HD / 2);
        rope_kernel<<<(tq + 255) / 256, 256>>>(qp, fc, fs, N_HEADS);
        int tk = S_LEN * N_KV * (HD / 2);
        rope_kernel<<<(tk + 255) / 256, 256>>>(kp, fc, fs, N_KV);
    }

    // Attention
    {
        int smem_bytes = (3 * QT * ROWP + QT * SSP) * (int)sizeof(float);  // ~115 KB
        cudaFuncSetAttribute(attn_kernel, cudaFuncAttributeMaxDynamicSharedMemorySize,
                             smem_bytes);
        attn_kernel<<<dim3(S_LEN / QT, N_HEADS), 256, smem_bytes>>>(qp, kp, vp, ap);
    }

    // Output projection
    sgemm_kernel<<<dim3(D_MODEL / BN, S_LEN / BM), 256>>>(ap, wo, out, S_LEN, D_MODEL, D_MODEL);
}

// round 3
// speedup vs baseline: 1.3372x; 1.3372x over previous
#include <cuda_runtime.h>
#include <cuda_bf16.h>
#include <cstdint>

// Shapes (fixed)
#define S_LEN 2048
#define D_MODEL 4096
#define N_HEADS 32
#define N_KV 8
#define HD 128

// Scratch (allocation-free rule: device globals)
__device__ float g_q[S_LEN * N_HEADS * HD];
__device__ float g_k[S_LEN * N_KV * HD];
__device__ float g_v[S_LEN * N_KV * HD];
__device__ float g_attn[S_LEN * N_HEADS * HD];
__device__ float g_xr[S_LEN * D_MODEL];        // tf32-rounded x
__device__ float g_wqT[4096 * 4096];
__device__ float g_wkT[1024 * 4096];
__device__ float g_wvT[1024 * 4096];
__device__ float g_woT[4096 * 4096];

// ---------------------------------------------------------------------------
// Helpers (all baseline-PTX: sm_80/sm_90 features only, no 'a'-gated instrs)
// ---------------------------------------------------------------------------
__device__ __forceinline__ uint32_t smem_u32(const void* p) {
    uint32_t a;
    asm("{ .reg .u64 t; cvta.to.shared.u64 t, %1; cvt.u32.u64 %0, t; }" : "=r"(a) : "l"(p));
    return a;
}
__device__ __forceinline__ float tf32r(float x) {
    uint32_t u;
    asm("cvt.rna.tf32.f32 %0, %1;" : "=r"(u) : "f"(x));
    return __uint_as_float(u);
}
#define MBARRIER_INIT(mbar, cnt) \
    asm volatile("mbarrier.init.shared.b64 [%0], %1;" :: "r"((uint32_t)(mbar)), "r"((uint32_t)(cnt)) : "memory")
#define MBARRIER_EXPECT_TX(mbar, bytes) \
    asm volatile("mbarrier.arrive.expect_tx.shared.b64 _, [%0], %1;" :: "r"((uint32_t)(mbar)), "r"((uint32_t)(bytes)) : "memory")
#define MBARRIER_WAIT_PARITY(mbar, par) do {                                        \
    uint32_t _m = (uint32_t)(mbar); uint32_t _p = (uint32_t)(par); uint32_t _d;     \
    asm volatile("{\n\t.reg .pred p;\n\t"                                           \
        "mbarrier.try_wait.parity.acquire.cta.shared::cta.b64 p, [%1], %2;\n\t"     \
        "selp.b32 %0, 1, 0, p;\n\t}" : "=r"(_d) : "r"(_m), "r"(_p) : "memory");     \
    if (!_d) {                                                                      \
        asm volatile("{\n\t.reg .pred P1;\n\t"                                      \
            "WL_%=:\n\t"                                                            \
            "mbarrier.try_wait.parity.acquire.cta.shared::cta.b64 P1, [%0], %1, 0x989680;\n\t" \
            "@P1 bra.uni WD_%=;\n\t"                                                \
            "bra.uni WL_%=;\n\t"                                                    \
            "WD_%=:\n\t}" :: "r"(_m), "r"(_p) : "memory");                          \
    }                                                                               \
} while (0)

__device__ __forceinline__ void bulk_g2s(uint32_t dst, const void* src,
                                         uint32_t bytes, uint32_t mbar) {
    asm volatile(
        "cp.async.bulk.shared::cluster.global.mbarrier::complete_tx::bytes [%0], [%1], %2, [%3];"
        :: "r"(dst), "l"(src), "r"(bytes), "r"(mbar) : "memory");
}

__device__ __forceinline__ void mma16n8k8(float* d, const uint32_t* a, const uint32_t* b) {
    asm volatile(
        "mma.sync.aligned.m16n8k8.row.col.f32.tf32.tf32.f32 "
        "{%0,%1,%2,%3}, {%4,%5,%6,%7}, {%8,%9}, {%0,%1,%2,%3};"
        : "+f"(d[0]), "+f"(d[1]), "+f"(d[2]), "+f"(d[3])
        : "r"(a[0]), "r"(a[1]), "r"(a[2]), "r"(a[3]), "r"(b[0]), "r"(b[1]));
}

// ---------------------------------------------------------------------------
// tf32 mma.sync GEMM: C[M,N] = A[M,K] @ Bt[N,K]^T. A, Bt pre-rounded to tf32.
// Tile 128x128, BK=32 floats, 3-stage cp.async.bulk pipeline.
// smem operand layout: [row][k] pitch 36 floats -> conflict-free frag LDS.
// ---------------------------------------------------------------------------
#define PITCHF 36
#define OPBYTES (128 * PITCHF * 4)       // 18432 per operand per stage
#define STAGE_BYTES (2 * OPBYTES)        // 36864
#define NSTG 3
#define GEMM_SMEM (1024 + NSTG * STAGE_BYTES)  // 111616

__global__ __launch_bounds__(256, 2)
void mma_gemm(const float* __restrict__ A, const float* __restrict__ Bt,
              float* __restrict__ C, int M, int N, int K) {
    extern __shared__ char smem[];
    const uint32_t sb = smem_u32(smem);
    const int tid = threadIdx.x;
    const int wid = tid >> 5, lane = tid & 31;
    const int wm = wid & 3;               // warp m: 4 x 32 rows
    const int wn = wid >> 2;              // warp n: 2 x 64 cols
    const int mlane = lane >> 2;          // 0..7
    const int klane = lane & 3;           // 0..3
    const int row0 = blockIdx.y * 128;
    const int col0 = blockIdx.x * 128;
    const int nk = K / 32;

    if (tid == 0) {
#pragma unroll
        for (int s = 0; s < NSTG; s++) MBARRIER_INIT(sb + 8 * s, 1);
    }
    __syncthreads();

    auto issue = [&](int kt, int st) {
        const int k0 = kt * 32;
        const uint32_t base = sb + 1024 + st * STAGE_BYTES;
        const uint32_t mbar = sb + 8 * st;
        if (tid < 128) {
            bulk_g2s(base + tid * (PITCHF * 4),
                     A + (size_t)(row0 + tid) * K + k0, 128, mbar);
        } else {
            int r = tid - 128;
            bulk_g2s(base + OPBYTES + r * (PITCHF * 4),
                     Bt + (size_t)(col0 + r) * K + k0, 128, mbar);
        }
    };

    // Prologue: stages 0 and 1
    if (tid == 0) MBARRIER_EXPECT_TX(sb + 0, 32768);
    issue(0, 0);
    if (tid == 0) MBARRIER_EXPECT_TX(sb + 8, 32768);
    issue(1, 1);

    float acc[2][8][4];
#pragma unroll
    for (int mi = 0; mi < 2; mi++)
#pragma unroll
        for (int ni = 0; ni < 8; ni++)
#pragma unroll
            for (int j = 0; j < 4; j++) acc[mi][ni][j] = 0.f;

    int cst = 0, cph = 0;                 // consumer cursor
    int pk = 2, pst = 2;                  // producer cursor

    for (int it = 0; it < nk; it++) {
        __syncthreads();
        if (pk < nk) {
            if (tid == 0) MBARRIER_EXPECT_TX(sb + 8 * pst, 32768);
            issue(pk, pst);
            pk++; pst++; if (pst == NSTG) pst = 0;
        }
        MBARRIER_WAIT_PARITY(sb + 8 * cst, cph);

        const float* As = (const float*)(smem + 1024 + cst * STAGE_BYTES);
        const float* Bs = As + 128 * PITCHF;

#pragma unroll
        for (int ks = 0; ks < 32; ks += 8) {
            uint32_t a[2][4], b[8][2];
#pragma unroll
            for (int mi = 0; mi < 2; mi++) {
                int r = wm * 32 + mi * 16 + mlane;
                a[mi][0] = __float_as_uint(As[r * PITCHF + ks + klane]);
                a[mi][1] = __float_as_uint(As[(r + 8) * PITCHF + ks + klane]);
                a[mi][2] = __float_as_uint(As[r * PITCHF + ks + klane + 4]);
                a[mi][3] = __float_as_uint(As[(r + 8) * PITCHF + ks + klane + 4]);
            }
#pragma unroll
            for (int ni = 0; ni < 8; ni++) {
                int rb = wn * 64 + ni * 8 + mlane;
                b[ni][0] = __float_as_uint(Bs[rb * PITCHF + ks + klane]);
                b[ni][1] = __float_as_uint(Bs[rb * PITCHF + ks + klane + 4]);
            }
#pragma unroll
            for (int mi = 0; mi < 2; mi++)
#pragma unroll
                for (int ni = 0; ni < 8; ni++)
                    mma16n8k8(acc[mi][ni], a[mi], b[ni]);
        }

        cst++; if (cst == NSTG) { cst = 0; cph ^= 1; }
    }

    // Epilogue
#pragma unroll
    for (int mi = 0; mi < 2; mi++) {
        int row = row0 + wm * 32 + mi * 16 + mlane;
#pragma unroll
        for (int ni = 0; ni < 8; ni++) {
            int col = col0 + wn * 64 + ni * 8 + 2 * klane;
            *(float2*)&C[(size_t)row * N + col] =
                make_float2(acc[mi][ni][0], acc[mi][ni][1]);
            *(float2*)&C[(size_t)(row + 8) * N + col] =
                make_float2(acc[mi][ni][2], acc[mi][ni][3]);
        }
    }
}

// ---------------------------------------------------------------------------
// Transpose + tf32 round: W[R][C] -> Wt[C][R]
// ---------------------------------------------------------------------------
__global__ void transpose_kernel(const float* __restrict__ W, float* __restrict__ Wt,
                                 int R, int C) {
    __shared__ float t[32][33];
    int bx = blockIdx.x * 32;
    int by = blockIdx.y * 32;
    int tx = threadIdx.x, ty = threadIdx.y;
#pragma unroll
    for (int i = 0; i < 32; i += 8)
        t[ty + i][tx] = W[(size_t)(by + ty + i) * C + bx + tx];
    __syncthreads();
#pragma unroll
    for (int i = 0; i < 32; i += 8)
        Wt[(size_t)(bx + ty + i) * R + by + tx] = tf32r(t[tx][ty + i]);
}

// ---------------------------------------------------------------------------
// tf32 rounding copy (for activations)
// ---------------------------------------------------------------------------
__global__ void round_tf32_kernel(const float* __restrict__ in, float* __restrict__ out, int n4) {
    int i = blockIdx.x * blockDim.x + threadIdx.x;
    if (i >= n4) return;
    float4 v = ((const float4*)in)[i];
    v.x = tf32r(v.x); v.y = tf32r(v.y); v.z = tf32r(v.z); v.w = tf32r(v.w);
    ((float4*)out)[i] = v;
}

// ---------------------------------------------------------------------------
// RoPE in-place on [S, Hn, 128]
// ---------------------------------------------------------------------------
__global__ void rope_kernel(float* __restrict__ t,
                            const float* __restrict__ cosb,
                            const float* __restrict__ sinb, int Hn) {
    int idx = blockIdx.x * blockDim.x + threadIdx.x;
    int total = S_LEN * Hn * (HD / 2);
    if (idx >= total) return;
    int i = idx & 63;
    int h = (idx >> 6) % Hn;
    int s = idx / (64 * Hn);
    float c = cosb[s * 64 + i];
    float sn = sinb[s * 64 + i];
    float* p = t + ((size_t)(s * Hn + h) * HD) + 2 * i;
    float a = p[0], b = p[1];
    p[0] = a * c - b * sn;
    p[1] = a * sn + b * c;
}

// ---------------------------------------------------------------------------
// Flash-style causal attention (fp32 SIMT). Output tf32-rounded for W_o GEMM.
// ---------------------------------------------------------------------------
#define QT 64
#define KT 64
#define ROWP 132
#define SSP 65

__global__ __launch_bounds__(256, 1)
void attn_kernel(const float* __restrict__ Q, const float* __restrict__ K,
                 const float* __restrict__ V, float* __restrict__ O) {
    extern __shared__ float smemf[];
    float* Qs = smemf;
    float* Ks = Qs + QT * ROWP;
    float* Vs = Ks + KT * ROWP;
    float* Ss = Vs + KT * ROWP;

    const int h = blockIdx.y;
    const int kvh = h >> 2;
    const int q0 = blockIdx.x * QT;
    const int tid = threadIdx.x;

    for (int i = tid; i < QT * 32; i += 256) {
        int r = i >> 5, c = (i & 31) * 4;
        *(float4*)&Qs[r * ROWP + c] =
            *(const float4*)&Q[((size_t)(q0 + r) * N_HEADS + h) * HD + c];
    }

    const int qi = tid >> 2;
    const int dgrp = tid & 3;

    float4 acc4[8];
#pragma unroll
    for (int i = 0; i < 8; i++) acc4[i] = make_float4(0.f, 0.f, 0.f, 0.f);
    float m = -1e30f, l = 0.f;
    const float scale = 0.08838834764831845f;

    const int kmax = q0 + QT;

    for (int k0 = 0; k0 < kmax; k0 += KT) {
        for (int i = tid; i < KT * 32; i += 256) {
            int r = i >> 5, c = (i & 31) * 4;
            size_t gidx = ((size_t)(k0 + r) * N_KV + kvh) * HD + c;
            *(float4*)&Ks[r * ROWP + c] = *(const float4*)&K[gidx];
            *(float4*)&Vs[r * ROWP + c] = *(const float4*)&V[gidx];
        }
        __syncthreads();

        {
            const int r = tid >> 2;
            const int cb = (tid & 3) * 16;
            const int qg = q0 + r;
            const float4* qr = (const float4*)(Qs + r * ROWP);
            float sc[16];
#pragma unroll
            for (int j = 0; j < 16; j++) sc[j] = 0.f;
            for (int d = 0; d < 32; d++) {
                float4 a = qr[d];
#pragma unroll
                for (int j = 0; j < 16; j++) {
                    float4 b = *(const float4*)(Ks + (cb + j) * ROWP + d * 4);
                    sc[j] += a.x * b.x + a.y * b.y + a.z * b.z + a.w * b.w;
                }
            }
#pragma unroll
            for (int j = 0; j < 16; j++) {
                int kg = k0 + cb + j;
                Ss[r * SSP + cb + j] = (kg <= qg) ? sc[j] * scale : -1e30f;
            }
        }
        __syncthreads();

        float mnew = m;
#pragma unroll
        for (int c = 0; c < KT; c++) mnew = fmaxf(mnew, Ss[qi * SSP + c]);
        float corr = __expf(m - mnew);
        l *= corr;
#pragma unroll
        for (int i = 0; i < 8; i++) {
            acc4[i].x *= corr; acc4[i].y *= corr;
            acc4[i].z *= corr; acc4[i].w *= corr;
        }
        for (int c = 0; c < KT; c++) {
            float p = __expf(Ss[qi * SSP + c] - mnew);
            l += p;
            const float4* vr = (const float4*)(Vs + c * ROWP + dgrp * 32);
#pragma unroll
            for (int i = 0; i < 8; i++) {
                float4 v = vr[i];
                acc4[i].x += p * v.x; acc4[i].y += p * v.y;
                acc4[i].z += p * v.z; acc4[i].w += p * v.w;
            }
        }
        m = mnew;
        __syncthreads();
    }

    float inv = 1.f / l;
    float* op = &O[((size_t)(q0 + qi) * N_HEADS + h) * HD + dgrp * 32];
#pragma unroll
    for (int i = 0; i < 8; i++) {
        *(float4*)(op + i * 4) = make_float4(tf32r(acc4[i].x * inv), tf32r(acc4[i].y * inv),
                                             tf32r(acc4[i].z * inv), tf32r(acc4[i].w * inv));
    }
}

// ---------------------------------------------------------------------------
// Host launcher
// ---------------------------------------------------------------------------
extern "C" void kernel_launch(void* const* d_in, const int* in_sizes, int n_in,
                              void* d_out, int out_size) {
    const float* x  = (const float*)d_in[0];
    const float* fc = (const float*)d_in[1];
    const float* fs = (const float*)d_in[2];
    const float* wq = (const float*)d_in[4];
    const float* wk = (const float*)d_in[5];
    const float* wv = (const float*)d_in[6];
    const float* wo = (const float*)d_in[7];
    float* out = (float*)d_out;

    float *qp, *kp, *vp, *ap, *xr, *wqT, *wkT, *wvT, *woT;
    cudaGetSymbolAddress((void**)&qp, g_q);
    cudaGetSymbolAddress((void**)&kp, g_k);
    cudaGetSymbolAddress((void**)&vp, g_v);
    cudaGetSymbolAddress((void**)&ap, g_attn);
    cudaGetSymbolAddress((void**)&xr, g_xr);
    cudaGetSymbolAddress((void**)&wqT, g_wqT);
    cudaGetSymbolAddress((void**)&wkT, g_wkT);
    cudaGetSymbolAddress((void**)&wvT, g_wvT);
    cudaGetSymbolAddress((void**)&woT, g_woT);

    // Transpose + tf32-round weights: W[K,N] -> Wt[N,K]
    transpose_kernel<<<dim3(4096 / 32, 4096 / 32), dim3(32, 8)>>>(wq, wqT, 4096, 4096);
    transpose_kernel<<<dim3(1024 / 32, 4096 / 32), dim3(32, 8)>>>(wk, wkT, 4096, 1024);
    transpose_kernel<<<dim3(1024 / 32, 4096 / 32), dim3(32, 8)>>>(wv, wvT, 4096, 1024);
    transpose_kernel<<<dim3(4096 / 32, 4096 / 32), dim3(32, 8)>>>(wo, woT, 4096, 4096);

    // tf32-round x
    {
        int n4 = S_LEN * D_MODEL / 4;
        round_tf32_kernel<<<(n4 + 255) / 256, 256>>>(x, xr, n4);
    }

    cudaFuncSetAttribute(mma_gemm, cudaFuncAttributeMaxDynamicSharedMemorySize, GEMM_SMEM);

    // QKV projections (tf32 mma.sync)
    mma_gemm<<<dim3(4096 / 128, S_LEN / 128), 256, GEMM_SMEM>>>(xr, wqT, qp, S_LEN, 4096, 4096);
    mma_gemm<<<dim3(1024 / 128, S_LEN / 128), 256, GEMM_SMEM>>>(xr, wkT, kp, S_LEN, 1024, 4096);
    mma_gemm<<<dim3(1024 / 128, S_LEN / 128), 256, GEMM_SMEM>>>(xr, wvT, vp, S_LEN, 1024, 4096);

    // RoPE
    {
        int tq = S_LEN * N_HEADS * (HD / 2);
        rope_kernel<<<(tq + 255) / 256, 256>>>(qp, fc, fs, N_HEADS);
        int tk = S_LEN * N_KV * (HD / 2);
        rope_kernel<<<(tk + 255) / 256, 256>>>(kp, fc, fs, N_KV);
    }

    // Attention (fp32 SIMT, tf32-rounded output)
    {
        int smem_bytes = (3 * QT * ROWP + QT * SSP) * (int)sizeof(float);
        cudaFuncSetAttribute(attn_kernel, cudaFuncAttributeMaxDynamicSharedMemorySize,
                             smem_bytes);
        attn_kernel<<<dim3(S_LEN / QT, N_HEADS), 256, smem_bytes>>>(qp, kp, vp, ap);
    }

    // Output projection
    mma_gemm<<<dim3(4096 / 128, S_LEN / 128), 256, GEMM_SMEM>>>(ap, woT, out, S_LEN, 4096, 4096);
}

// round 4
// speedup vs baseline: 1.4405x; 1.0772x over previous
#include <cuda_runtime.h>
#include <cuda_bf16.h>
#include <cstdint>

// Shapes (fixed)
#define S_LEN 2048
#define D_MODEL 4096
#define N_HEADS 32
#define N_KV 8
#define HD 128

// Scratch (allocation-free rule: device globals)
__device__ float g_q[S_LEN * N_HEADS * HD];
__device__ float g_k[S_LEN * N_KV * HD];
__device__ float g_v[S_LEN * N_KV * HD];
__device__ float g_attn[S_LEN * N_HEADS * HD];   // packed-tile layout
__device__ float g_xp[S_LEN * D_MODEL];          // packed-tile, tf32-rounded x
__device__ float g_wqT[4096 * 4096];             // packed-tile
__device__ float g_wkT[1024 * 4096];
__device__ float g_wvT[1024 * 4096];
__device__ float g_woT[4096 * 4096];

// Packed tile layout: tensor [Nrows, K] -> [rowblk][chunk][128x32 tile]
// tile inner offset (floats): SWZ(r, k) for r in 0..127, k in 0..31
#define SWZ(r, k) (((r) << 5) + ((k) ^ (((r) & 7) << 2)))

// ---------------------------------------------------------------------------
// Helpers (baseline PTX only: no 'a'-gated instructions)
// ---------------------------------------------------------------------------
__device__ __forceinline__ uint32_t smem_u32(const void* p) {
    uint32_t a;
    asm("{ .reg .u64 t; cvta.to.shared.u64 t, %1; cvt.u32.u64 %0, t; }" : "=r"(a) : "l"(p));
    return a;
}
__device__ __forceinline__ float tf32r(float x) {
    uint32_t u;
    asm("cvt.rna.tf32.f32 %0, %1;" : "=r"(u) : "f"(x));
    return __uint_as_float(u);
}
#define MBARRIER_INIT(mbar, cnt) \
    asm volatile("mbarrier.init.shared.b64 [%0], %1;" :: "r"((uint32_t)(mbar)), "r"((uint32_t)(cnt)) : "memory")
#define MBARRIER_EXPECT_TX(mbar, bytes) \
    asm volatile("mbarrier.arrive.expect_tx.shared.b64 _, [%0], %1;" :: "r"((uint32_t)(mbar)), "r"((uint32_t)(bytes)) : "memory")
#define MBARRIER_WAIT_PARITY(mbar, par) do {                                        \
    uint32_t _m = (uint32_t)(mbar); uint32_t _p = (uint32_t)(par); uint32_t _d;     \
    asm volatile("{\n\t.reg .pred p;\n\t"                                           \
        "mbarrier.try_wait.parity.acquire.cta.shared::cta.b64 p, [%1], %2;\n\t"     \
        "selp.b32 %0, 1, 0, p;\n\t}" : "=r"(_d) : "r"(_m), "r"(_p) : "memory");     \
    if (!_d) {                                                                      \
        asm volatile("{\n\t.reg .pred P1;\n\t"                                      \
            "WL_%=:\n\t"                                                            \
            "mbarrier.try_wait.parity.acquire.cta.shared::cta.b64 P1, [%0], %1, 0x989680;\n\t" \
            "@P1 bra.uni WD_%=;\n\t"                                                \
            "bra.uni WL_%=;\n\t"                                                    \
            "WD_%=:\n\t}" :: "r"(_m), "r"(_p) : "memory");                          \
    }                                                                               \
} while (0)

__device__ __forceinline__ void bulk_g2s(uint32_t dst, const void* src,
                                         uint32_t bytes, uint32_t mbar) {
    asm volatile(
        "cp.async.bulk.shared::cluster.global.mbarrier::complete_tx::bytes [%0], [%1], %2, [%3];"
        :: "r"(dst), "l"(src), "r"(bytes), "r"(mbar) : "memory");
}

__device__ __forceinline__ void mma16n8k8(float* d, const uint32_t* a, const uint32_t* b) {
    asm volatile(
        "mma.sync.aligned.m16n8k8.row.col.f32.tf32.tf32.f32 "
        "{%0,%1,%2,%3}, {%4,%5,%6,%7}, {%8,%9}, {%0,%1,%2,%3};"
        : "+f"(d[0]), "+f"(d[1]), "+f"(d[2]), "+f"(d[3])
        : "r"(a[0]), "r"(a[1]), "r"(a[2]), "r"(a[3]), "r"(b[0]), "r"(b[1]));
}

// ---------------------------------------------------------------------------
// tf32 mma.sync GEMM on packed-tile operands.
// C[M,N] = A @ B^T conceptually; Ap/Bp are [blk][chunk][128x32 swizzled].
// Tile 128x128, BK=32, 3-stage pipeline, 2 bulk ops (16 KB) per stage.
// ---------------------------------------------------------------------------
#define TILE_F 4096                        // floats per 128x32 tile
#define TILE_B 16384                       // bytes per tile
#define STAGE_F (2 * TILE_F)
#define STAGE_B (2 * TILE_B)               // 32768
#define NSTG 3
#define GEMM_SMEM (1024 + NSTG * STAGE_B)  // 99328

__global__ __launch_bounds__(256, 2)
void mma_gemm(const float* __restrict__ Ap, const float* __restrict__ Bp,
              float* __restrict__ C, int M, int N, int K) {
    extern __shared__ char smem[];
    const uint32_t sb = smem_u32(smem);
    const int tid = threadIdx.x;
    const int wid = tid >> 5, lane = tid & 31;
    const int wm = wid & 3;               // 4 warps over M (32 rows each)
    const int wn = wid >> 2;              // 2 warps over N (64 cols each)
    const int mlane = lane >> 2;          // 0..7
    const int klane = lane & 3;           // 0..3
    const int nch = K >> 5;

    if (tid == 0) {
#pragma unroll
        for (int s = 0; s < NSTG; s++) MBARRIER_INIT(sb + 8 * s, 1);
    }
    __syncthreads();

    const float* Abase = Ap + (size_t)blockIdx.y * nch * TILE_F;
    const float* Bbase = Bp + (size_t)blockIdx.x * nch * TILE_F;

    auto issue = [&](int chunk, int st) {
        uint32_t base = sb + 1024 + st * STAGE_B;
        MBARRIER_EXPECT_TX(sb + 8 * st, STAGE_B);
        bulk_g2s(base, Abase + (size_t)chunk * TILE_F, TILE_B, sb + 8 * st);
        bulk_g2s(base + TILE_B, Bbase + (size_t)chunk * TILE_F, TILE_B, sb + 8 * st);
    };

    if (tid == 0) { issue(0, 0); issue(1, 1); }

    float acc[2][8][4];
#pragma unroll
    for (int mi = 0; mi < 2; mi++)
#pragma unroll
        for (int ni = 0; ni < 8; ni++)
#pragma unroll
            for (int j = 0; j < 4; j++) acc[mi][ni][j] = 0.f;

    int cst = 0, cph = 0;
    int pk = 2, pst = 2;

    for (int it = 0; it < nch; it++) {
        __syncthreads();
        if (pk < nch) {
            if (tid == 0) issue(pk, pst);
            pk++; pst++; if (pst == NSTG) pst = 0;
        }
        MBARRIER_WAIT_PARITY(sb + 8 * cst, cph);

        const float* As = (const float*)(smem + 1024 + cst * STAGE_B);
        const float* Bs = As + TILE_F;

#pragma unroll
        for (int ks = 0; ks < 32; ks += 8) {
            uint32_t a[2][4], b[8][2];
#pragma unroll
            for (int mi = 0; mi < 2; mi++) {
                int r = wm * 32 + mi * 16 + mlane;
                a[mi][0] = __float_as_uint(As[SWZ(r, ks + klane)]);
                a[mi][1] = __float_as_uint(As[SWZ(r + 8, ks + klane)]);
                a[mi][2] = __float_as_uint(As[SWZ(r, ks + klane + 4)]);
                a[mi][3] = __float_as_uint(As[SWZ(r + 8, ks + klane + 4)]);
            }
#pragma unroll
            for (int ni = 0; ni < 8; ni++) {
                int rb = wn * 64 + ni * 8 + mlane;
                b[ni][0] = __float_as_uint(Bs[SWZ(rb, ks + klane)]);
                b[ni][1] = __float_as_uint(Bs[SWZ(rb, ks + klane + 4)]);
            }
#pragma unroll
            for (int mi = 0; mi < 2; mi++)
#pragma unroll
                for (int ni = 0; ni < 8; ni++)
                    mma16n8k8(acc[mi][ni], a[mi], b[ni]);
        }

        cst++; if (cst == NSTG) { cst = 0; cph ^= 1; }
    }

    const int row0 = blockIdx.y * 128;
    const int col0 = blockIdx.x * 128;
#pragma unroll
    for (int mi = 0; mi < 2; mi++) {
        int row = row0 + wm * 32 + mi * 16 + mlane;
#pragma unroll
        for (int ni = 0; ni < 8; ni++) {
            int col = col0 + wn * 64 + ni * 8 + 2 * klane;
            *(float2*)&C[(size_t)row * N + col] =
                make_float2(acc[mi][ni][0], acc[mi][ni][1]);
            *(float2*)&C[(size_t)(row + 8) * N + col] =
                make_float2(acc[mi][ni][2], acc[mi][ni][3]);
        }
    }
}

// ---------------------------------------------------------------------------
// Transpose + tf32 round + pack: W[R=K][C=N] -> packed [colblk][chunk][tile]
// ---------------------------------------------------------------------------
__global__ void transpose_pack_kernel(const float* __restrict__ W, float* __restrict__ P,
                                      int R, int C) {
    __shared__ float t[32][33];
    int bx = blockIdx.x * 32;   // N offset
    int by = blockIdx.y * 32;   // K offset
    int tx = threadIdx.x, ty = threadIdx.y;
#pragma unroll
    for (int i = 0; i < 32; i += 8)
        t[ty + i][tx] = W[(size_t)(by + ty + i) * C + bx + tx];
    __syncthreads();
    const int nch = R >> 5;
    const int chunk = by >> 5;  // k-chunk (fixed per block)
#pragma unroll
    for (int i = 0; i < 32; i += 8) {
        int n = bx + ty + i;     // output row (col of W)
        int colblk = n >> 7, r = n & 127;
        int kin = tx;            // k within chunk
        P[((size_t)colblk * nch + chunk) * TILE_F + SWZ(r, kin)] = tf32r(t[tx][ty + i]);
    }
}

// ---------------------------------------------------------------------------
// tf32 round + pack activations: X[M,K] -> packed [rowblk][chunk][tile]
// ---------------------------------------------------------------------------
__global__ void pack_x_kernel(const float* __restrict__ X, float* __restrict__ P, int K) {
    int idx = blockIdx.x * blockDim.x + threadIdx.x;  // one float4 each
    int perrow = K >> 2;
    int s = idx / perrow;
    int d4 = (idx % perrow) << 2;
    float4 v = *(const float4*)&X[(size_t)s * K + d4];
    v.x = tf32r(v.x); v.y = tf32r(v.y); v.z = tf32r(v.z); v.w = tf32r(v.w);
    int rowblk = s >> 7, r = s & 127;
    int chunk = d4 >> 5, k = d4 & 31;
    int nch = K >> 5;
    *(float4*)&P[((size_t)rowblk * nch + chunk) * TILE_F + SWZ(r, k)] = v;
}

// ---------------------------------------------------------------------------
// RoPE in-place on [S, Hn, 128]
// ---------------------------------------------------------------------------
__global__ void rope_kernel(float* __restrict__ t,
                            const float* __restrict__ cosb,
                            const float* __restrict__ sinb, int Hn) {
    int idx = blockIdx.x * blockDim.x + threadIdx.x;
    int total = S_LEN * Hn * (HD / 2);
    if (idx >= total) return;
    int i = idx & 63;
    int h = (idx >> 6) % Hn;
    int s = idx / (64 * Hn);
    float c = cosb[s * 64 + i];
    float sn = sinb[s * 64 + i];
    float* p = t + ((size_t)(s * Hn + h) * HD) + 2 * i;
    float a = p[0], b = p[1];
    p[0] = a * c - b * sn;
    p[1] = a * sn + b * c;
}

// ---------------------------------------------------------------------------
// Flash-style causal attention (fp32 SIMT). Writes tf32-rounded PACKED output.
// ---------------------------------------------------------------------------
#define QT 64
#define KT 64
#define ROWP 132
#define SSP 65

__global__ __launch_bounds__(256, 1)
void attn_kernel(const float* __restrict__ Q, const float* __restrict__ K,
                 const float* __restrict__ V, float* __restrict__ O) {
    extern __shared__ float smemf[];
    float* Qs = smemf;
    float* Ks = Qs + QT * ROWP;
    float* Vs = Ks + KT * ROWP;
    float* Ss = Vs + KT * ROWP;

    const int h = blockIdx.y;
    const int kvh = h >> 2;
    const int q0 = blockIdx.x * QT;
    const int tid = threadIdx.x;

    for (int i = tid; i < QT * 32; i += 256) {
        int r = i >> 5, c = (i & 31) * 4;
        *(float4*)&Qs[r * ROWP + c] =
            *(const float4*)&Q[((size_t)(q0 + r) * N_HEADS + h) * HD + c];
    }

    const int qi = tid >> 2;
    const int dgrp = tid & 3;

    float4 acc4[8];
#pragma unroll
    for (int i = 0; i < 8; i++) acc4[i] = make_float4(0.f, 0.f, 0.f, 0.f);
    float m = -1e30f, l = 0.f;
    const float scale = 0.08838834764831845f;

    const int kmax = q0 + QT;

    for (int k0 = 0; k0 < kmax; k0 += KT) {
        for (int i = tid; i < KT * 32; i += 256) {
            int r = i >> 5, c = (i & 31) * 4;
            size_t gidx = ((size_t)(k0 + r) * N_KV + kvh) * HD + c;
            *(float4*)&Ks[r * ROWP + c] = *(const float4*)&K[gidx];
            *(float4*)&Vs[r * ROWP + c] = *(const float4*)&V[gidx];
        }
        __syncthreads();

        {
            const int r = tid >> 2;
            const int cb = (tid & 3) * 16;
            const int qg = q0 + r;
            const float4* qr = (const float4*)(Qs + r * ROWP);
            float sc[16];
#pragma unroll
            for (int j = 0; j < 16; j++) sc[j] = 0.f;
            for (int d = 0; d < 32; d++) {
                float4 a = qr[d];
#pragma unroll
                for (int j = 0; j < 16; j++) {
                    float4 b = *(const float4*)(Ks + (cb + j) * ROWP + d * 4);
                    sc[j] += a.x * b.x + a.y * b.y + a.z * b.z + a.w * b.w;
                }
            }
#pragma unroll
            for (int j = 0; j < 16; j++) {
                int kg = k0 + cb + j;
                Ss[r * SSP + cb + j] = (kg <= qg) ? sc[j] * scale : -1e30f;
            }
        }
        __syncthreads();

        float mnew = m;
#pragma unroll
        for (int c = 0; c < KT; c++) mnew = fmaxf(mnew, Ss[qi * SSP + c]);
        float corr = __expf(m - mnew);
        l *= corr;
#pragma unroll
        for (int i = 0; i < 8; i++) {
            acc4[i].x *= corr; acc4[i].y *= corr;
            acc4[i].z *= corr; acc4[i].w *= corr;
        }
        for (int c = 0; c < KT; c++) {
            float p = __expf(Ss[qi * SSP + c] - mnew);
            l += p;
            const float4* vr = (const float4*)(Vs + c * ROWP + dgrp * 32);
#pragma unroll
            for (int i = 0; i < 8; i++) {
                float4 v = vr[i];
                acc4[i].x += p * v.x; acc4[i].y += p * v.y;
                acc4[i].z += p * v.z; acc4[i].w += p * v.w;
            }
        }
        m = mnew;
        __syncthreads();
    }

    // Packed-tile epilogue: s-row -> (rowblk, r), dims h*128+dgrp*32.. -> chunk
    float inv = 1.f / l;
    const int s = q0 + qi;
    const int rowblk = s >> 7, rin = s & 127;
    const int chunk = h * 4 + dgrp;            // (h*128+dgrp*32)/32
    float* base = O + ((size_t)rowblk * 128 + chunk) * TILE_F;
#pragma unroll
    for (int i = 0; i < 8; i++) {
        float4 v = make_float4(tf32r(acc4[i].x * inv), tf32r(acc4[i].y * inv),
                               tf32r(acc4[i].z * inv), tf32r(acc4[i].w * inv));
        *(float4*)&base[SWZ(rin, i * 4)] = v;
    }
}

// ---------------------------------------------------------------------------
// Host launcher
// ---------------------------------------------------------------------------
extern "C" void kernel_launch(void* const* d_in, const int* in_sizes, int n_in,
                              void* d_out, int out_size) {
    const float* x  = (const float*)d_in[0];
    const float* fc = (const float*)d_in[1];
    const float* fs = (const float*)d_in[2];
    const float* wq = (const float*)d_in[4];
    const float* wk = (const float*)d_in[5];
    const float* wv = (const float*)d_in[6];
    const float* wo = (const float*)d_in[7];
    float* out = (float*)d_out;

    float *qp, *kp, *vp, *ap, *xp, *wqT, *wkT, *wvT, *woT;
    cudaGetSymbolAddress((void**)&qp, g_q);
    cudaGetSymbolAddress((void**)&kp, g_k);
    cudaGetSymbolAddress((void**)&vp, g_v);
    cudaGetSymbolAddress((void**)&ap, g_attn);
    cudaGetSymbolAddress((void**)&xp, g_xp);
    cudaGetSymbolAddress((void**)&wqT, g_wqT);
    cudaGetSymbolAddress((void**)&wkT, g_wkT);
    cudaGetSymbolAddress((void**)&wvT, g_wvT);
    cudaGetSymbolAddress((void**)&woT, g_woT);

    // Pack weights (transpose + tf32 + tile/swizzle)
    transpose_pack_kernel<<<dim3(4096 / 32, 4096 / 32), dim3(32, 8)>>>(wq, wqT, 4096, 4096);
    transpose_pack_kernel<<<dim3(1024 / 32, 4096 / 32), dim3(32, 8)>>>(wk, wkT, 4096, 1024);
    transpose_pack_kernel<<<dim3(1024 / 32, 4096 / 32), dim3(32, 8)>>>(wv, wvT, 4096, 1024);
    transpose_pack_kernel<<<dim3(4096 / 32, 4096 / 32), dim3(32, 8)>>>(wo, woT, 4096, 4096);

    // Pack activations
    {
        int n4 = S_LEN * D_MODEL / 4;
        pack_x_kernel<<<(n4 + 255) / 256, 256>>>(x, xp, D_MODEL);
    }

    cudaFuncSetAttribute(mma_gemm, cudaFuncAttributeMaxDynamicSharedMemorySize, GEMM_SMEM);

    // QKV projections (tf32 mma.sync, packed operands)
    mma_gemm<<<dim3(4096 / 128, S_LEN / 128), 256, GEMM_SMEM>>>(xp, wqT, qp, S_LEN, 4096, 4096);
    mma_gemm<<<dim3(1024 / 128, S_LEN / 128), 256, GEMM_SMEM>>>(xp, wkT, kp, S_LEN, 1024, 4096);
    mma_gemm<<<dim3(1024 / 128, S_LEN / 128), 256, GEMM_SMEM>>>(xp, wvT, vp, S_LEN, 1024, 4096);

    // RoPE
    {
        int tq = S_LEN * N_HEADS * (HD / 2);
        rope_kernel<<<(tq + 255) / 256, 256>>>(qp, fc, fs, N_HEADS);
        int tk = S_LEN * N_KV * (HD / 2);
        rope_kernel<<<(tk + 255) / 256, 256>>>(kp, fc, fs, N_KV);
    }

    // Attention (writes packed g_attn)
    {
        int smem_bytes = (3 * QT * ROWP + QT * SSP) * (int)sizeof(float);
        cudaFuncSetAttribute(attn_kernel, cudaFuncAttributeMaxDynamicSharedMemorySize,
                             smem_bytes);
        attn_kernel<<<dim3(S_LEN / QT, N_HEADS), 256, smem_bytes>>>(qp, kp, vp, ap);
    }

    // Output projection
    mma_gemm<<<dim3(4096 / 128, S_LEN / 128), 256, GEMM_SMEM>>>(ap, woT, out, S_LEN, 4096, 4096);
}

// round 5
// speedup vs baseline: 4.7992x; 3.3317x over previous
#include <cuda_runtime.h>
#include <cuda_fp16.h>
#include <cstdint>

// Shapes (fixed)
#define S_LEN 2048
#define D_MODEL 4096
#define N_HEADS 32
#define N_KV 8
#define HD 128

// Scratch (allocation-free rule: device globals)
__device__ float    g_q[S_LEN * N_HEADS * HD];
__device__ float    g_k[S_LEN * N_KV * HD];
__device__ float    g_v[S_LEN * N_KV * HD];
__device__ uint32_t g_attn[S_LEN * N_HEADS * HD / 2];   // fp16 packed tiles
__device__ uint32_t g_xp[S_LEN * D_MODEL / 2];          // fp16 packed x
__device__ uint32_t g_wqT[4096 * 4096 / 2];             // fp16 packed weights
__device__ uint32_t g_wkT[1024 * 4096 / 2];
__device__ uint32_t g_wvT[1024 * 4096 / 2];
__device__ uint32_t g_woT[4096 * 4096 / 2];

// Packed tile: [rowblk(128)][chunk(64 k)][128 x 32 half2], inner swizzled:
#define SWZ(r, c2) (((r) << 5) + ((c2) ^ (((r) & 7) << 2)))
#define TILE_U32 4096
#define TILE_B 16384

// ---------------------------------------------------------------------------
// Helpers (baseline PTX only)
// ---------------------------------------------------------------------------
__device__ __forceinline__ uint32_t smem_u32(const void* p) {
    uint32_t a;
    asm("{ .reg .u64 t; cvta.to.shared.u64 t, %1; cvt.u32.u64 %0, t; }" : "=r"(a) : "l"(p));
    return a;
}
#define MBARRIER_INIT(mbar, cnt) \
    asm volatile("mbarrier.init.shared.b64 [%0], %1;" :: "r"((uint32_t)(mbar)), "r"((uint32_t)(cnt)) : "memory")
#define MBARRIER_EXPECT_TX(mbar, bytes) \
    asm volatile("mbarrier.arrive.expect_tx.shared.b64 _, [%0], %1;" :: "r"((uint32_t)(mbar)), "r"((uint32_t)(bytes)) : "memory")
#define MBARRIER_WAIT_PARITY(mbar, par) do {                                        \
    uint32_t _m = (uint32_t)(mbar); uint32_t _p = (uint32_t)(par); uint32_t _d;     \
    asm volatile("{\n\t.reg .pred p;\n\t"                                           \
        "mbarrier.try_wait.parity.acquire.cta.shared::cta.b64 p, [%1], %2;\n\t"     \
        "selp.b32 %0, 1, 0, p;\n\t}" : "=r"(_d) : "r"(_m), "r"(_p) : "memory");     \
    if (!_d) {                                                                      \
        asm volatile("{\n\t.reg .pred P1;\n\t"                                      \
            "WL_%=:\n\t"                                                            \
            "mbarrier.try_wait.parity.acquire.cta.shared::cta.b64 P1, [%0], %1, 0x989680;\n\t" \
            "@P1 bra.uni WD_%=;\n\t"                                                \
            "bra.uni WL_%=;\n\t"                                                    \
            "WD_%=:\n\t}" :: "r"(_m), "r"(_p) : "memory");                          \
    }                                                                               \
} while (0)

__device__ __forceinline__ void bulk_g2s(uint32_t dst, const void* src,
                                         uint32_t bytes, uint32_t mbar) {
    asm volatile(
        "cp.async.bulk.shared::cluster.global.mbarrier::complete_tx::bytes [%0], [%1], %2, [%3];"
        :: "r"(dst), "l"(src), "r"(bytes), "r"(mbar) : "memory");
}

__device__ __forceinline__ void mma16816(float* d, const uint32_t* a, const uint32_t* b) {
    asm volatile(
        "mma.sync.aligned.m16n8k16.row.col.f32.f16.f16.f32 "
        "{%0,%1,%2,%3}, {%4,%5,%6,%7}, {%8,%9}, {%0,%1,%2,%3};"
        : "+f"(d[0]), "+f"(d[1]), "+f"(d[2]), "+f"(d[3])
        : "r"(a[0]), "r"(a[1]), "r"(a[2]), "r"(a[3]), "r"(b[0]), "r"(b[1]));
}

// ---------------------------------------------------------------------------
// fp16 mma.sync GEMM on packed-tile operands (C = A @ B^T, fp32 out).
// Tile 128x128, chunk = 64 k (16 KB/operand), 3-stage bulk-copy pipeline.
// ---------------------------------------------------------------------------
#define STAGE_B (2 * TILE_B)               // 32768
#define NSTG 3
#define GEMM_SMEM (1024 + NSTG * STAGE_B)  // 99328

__global__ __launch_bounds__(256, 2)
void mma_gemm(const uint32_t* __restrict__ Ap, const uint32_t* __restrict__ Bp,
              float* __restrict__ C, int M, int N, int K) {
    extern __shared__ char smem[];
    const uint32_t sb = smem_u32(smem);
    const int tid = threadIdx.x;
    const int wid = tid >> 5, lane = tid & 31;
    const int wm = wid & 3;               // 4 warps over M (32 rows each)
    const int wn = wid >> 2;              // 2 warps over N (64 cols each)
    const int mlane = lane >> 2;          // 0..7
    const int klane = lane & 3;           // 0..3
    const int nch = K >> 6;

    if (tid == 0) {
#pragma unroll
        for (int s = 0; s < NSTG; s++) MBARRIER_INIT(sb + 8 * s, 1);
    }
    __syncthreads();

    const uint32_t* Abase = Ap + (size_t)blockIdx.y * nch * TILE_U32;
    const uint32_t* Bbase = Bp + (size_t)blockIdx.x * nch * TILE_U32;

    auto issue = [&](int chunk, int st) {
        uint32_t base = sb + 1024 + st * STAGE_B;
        MBARRIER_EXPECT_TX(sb + 8 * st, STAGE_B);
        bulk_g2s(base, Abase + (size_t)chunk * TILE_U32, TILE_B, sb + 8 * st);
        bulk_g2s(base + TILE_B, Bbase + (size_t)chunk * TILE_U32, TILE_B, sb + 8 * st);
    };

    if (tid == 0) { issue(0, 0); issue(1, 1); }

    float acc[2][8][4];
#pragma unroll
    for (int mi = 0; mi < 2; mi++)
#pragma unroll
        for (int ni = 0; ni < 8; ni++)
#pragma unroll
            for (int j = 0; j < 4; j++) acc[mi][ni][j] = 0.f;

    int cst = 0, cph = 0;
    int pk = 2, pst = 2;

    for (int it = 0; it < nch; it++) {
        __syncthreads();
        if (pk < nch) {
            if (tid == 0) issue(pk, pst);
            pk++; pst++; if (pst == NSTG) pst = 0;
        }
        MBARRIER_WAIT_PARITY(sb + 8 * cst, cph);

        const uint32_t* As = (const uint32_t*)(smem + 1024 + cst * STAGE_B);
        const uint32_t* Bs = As + TILE_U32;

#pragma unroll
        for (int s = 0; s < 4; s++) {          // 4 x k16 steps (c2 base = s*8)
            const int c2b = s * 8;
            uint32_t a[2][4], b[8][2];
#pragma unroll
            for (int mi = 0; mi < 2; mi++) {
                int r = wm * 32 + mi * 16 + mlane;
                a[mi][0] = As[SWZ(r, c2b + klane)];
                a[mi][1] = As[SWZ(r + 8, c2b + klane)];
                a[mi][2] = As[SWZ(r, c2b + klane + 4)];
                a[mi][3] = As[SWZ(r + 8, c2b + klane + 4)];
            }
#pragma unroll
            for (int ni = 0; ni < 8; ni++) {
                int rb = wn * 64 + ni * 8 + mlane;
                b[ni][0] = Bs[SWZ(rb, c2b + klane)];
                b[ni][1] = Bs[SWZ(rb, c2b + klane + 4)];
            }
#pragma unroll
            for (int mi = 0; mi < 2; mi++)
#pragma unroll
                for (int ni = 0; ni < 8; ni++)
                    mma16816(acc[mi][ni], a[mi], b[ni]);
        }

        cst++; if (cst == NSTG) { cst = 0; cph ^= 1; }
    }

    const int row0 = blockIdx.y * 128;
    const int col0 = blockIdx.x * 128;
#pragma unroll
    for (int mi = 0; mi < 2; mi++) {
        int row = row0 + wm * 32 + mi * 16 + mlane;
#pragma unroll
        for (int ni = 0; ni < 8; ni++) {
            int col = col0 + wn * 64 + ni * 8 + 2 * klane;
            *(float2*)&C[(size_t)row * N + col] =
                make_float2(acc[mi][ni][0], acc[mi][ni][1]);
            *(float2*)&C[(size_t)(row + 8) * N + col] =
                make_float2(acc[mi][ni][2], acc[mi][ni][3]);
        }
    }
}

// ---------------------------------------------------------------------------
// Transpose + fp16 + pack: W[K=R][N=C] -> packed [colblk][chunk64][tile]
// ---------------------------------------------------------------------------
__global__ void transpose_pack_kernel(const float* __restrict__ W, uint32_t* __restrict__ P,
                                      int R, int C) {
    __shared__ float t[32][33];
    int bx = blockIdx.x * 32;   // N offset
    int by = blockIdx.y * 32;   // K offset
    int tx = threadIdx.x, ty = threadIdx.y;   // 32 x 8
#pragma unroll
    for (int i = 0; i < 32; i += 8)
        t[ty + i][tx] = W[(size_t)(by + ty + i) * C + bx + tx];
    __syncthreads();
    const int nch = R >> 6;
    const int kk2 = tx & 15;
    const int kglob = by + 2 * kk2;
    const int chunk = kglob >> 6;
    const int c2 = (kglob & 63) >> 1;
    const int nbase = (tx >> 4) * 8 + ty;
#pragma unroll
    for (int g = 0; g < 2; g++) {
        int nloc = nbase + g * 16;
        int n = bx + nloc;
        int colblk = n >> 7, r = n & 127;
        __half2 v = __floats2half2_rn(t[2 * kk2][nloc], t[2 * kk2 + 1][nloc]);
        P[((size_t)colblk * nch + chunk) * TILE_U32 + SWZ(r, c2)] = *(uint32_t*)&v;
    }
}

// ---------------------------------------------------------------------------
// fp16 + pack activations: X[M,K] fp32 -> packed [rowblk][chunk64][tile]
// ---------------------------------------------------------------------------
__global__ void pack_x_kernel(const float* __restrict__ X, uint32_t* __restrict__ P, int K) {
    int idx = blockIdx.x * blockDim.x + threadIdx.x;  // one float4 each
    int perrow = K >> 2;
    int s = idx / perrow;
    int d4 = (idx % perrow) << 2;
    float4 v = *(const float4*)&X[(size_t)s * K + d4];
    int rowblk = s >> 7, r = s & 127;
    int chunk = d4 >> 6;
    int c2 = (d4 & 63) >> 1;          // even
    int nch = K >> 6;
    __half2 lo = __floats2half2_rn(v.x, v.y);
    __half2 hi = __floats2half2_rn(v.z, v.w);
    uint32_t* dst = &P[((size_t)rowblk * nch + chunk) * TILE_U32 + SWZ(r, c2)];
    *(uint2*)dst = make_uint2(*(uint32_t*)&lo, *(uint32_t*)&hi);
}

// ---------------------------------------------------------------------------
// RoPE in-place on [S, Hn, 128] (fp32)
// ---------------------------------------------------------------------------
__global__ void rope_kernel(float* __restrict__ t,
                            const float* __restrict__ cosb,
                            const float* __restrict__ sinb, int Hn) {
    int idx = blockIdx.x * blockDim.x + threadIdx.x;
    int total = S_LEN * Hn * (HD / 2);
    if (idx >= total) return;
    int i = idx & 63;
    int h = (idx >> 6) % Hn;
    int s = idx / (64 * Hn);
    float c = cosb[s * 64 + i];
    float sn = sinb[s * 64 + i];
    float* p = t + ((size_t)(s * Hn + h) * HD) + 2 * i;
    float a = p[0], b = p[1];
    p[0] = a * c - b * sn;
    p[1] = a * sn + b * c;
}

// ---------------------------------------------------------------------------
// Flash-style causal attention, fp32 SIMT, conflict-free smem access.
// Writes fp16 packed-tile output for the O projection.
// ---------------------------------------------------------------------------
#define QT 64
#define KT 64
#define ROWP 132
#define SSP 68

__global__ __launch_bounds__(256, 1)
void attn_kernel(const float* __restrict__ Q, const float* __restrict__ K,
                 const float* __restrict__ V, uint32_t* __restrict__ O) {
    extern __shared__ float smemf[];
    float* Qs = smemf;
    float* Ks = Qs + QT * ROWP;
    float* Vs = Ks + KT * ROWP;
    float* Ss = Vs + KT * ROWP;

    const int h = blockIdx.y;
    const int kvh = h >> 2;
    const int q0 = blockIdx.x * QT;
    const int tid = threadIdx.x;

    for (int i = tid; i < QT * 32; i += 256) {
        int r = i >> 5, c = (i & 31) * 4;
        *(float4*)&Qs[r * ROWP + c] =
            *(const float4*)&Q[((size_t)(q0 + r) * N_HEADS + h) * HD + c];
    }

    const int qi = tid >> 2;          // query row (8 per warp)
    const int dgrp = tid & 3;         // dim-slice id

    float4 acc4[8];                   // dims dgrp*4 + i*16, i=0..7
#pragma unroll
    for (int i = 0; i < 8; i++) acc4[i] = make_float4(0.f, 0.f, 0.f, 0.f);
    float m = -1e30f, l = 0.f;
    const float scale = 0.08838834764831845f;

    const int kmax = q0 + QT;

    for (int k0 = 0; k0 < kmax; k0 += KT) {
        for (int i = tid; i < KT * 32; i += 256) {
            int r = i >> 5, c = (i & 31) * 4;
            size_t gidx = ((size_t)(k0 + r) * N_KV + kvh) * HD + c;
            *(float4*)&Ks[r * ROWP + c] = *(const float4*)&K[gidx];
            *(float4*)&Vs[r * ROWP + c] = *(const float4*)&V[gidx];
        }
        __syncthreads();

        // Scores: row r = tid>>2, cols c = cl + jj*4 (lane-adjacent -> bank-clean)
        {
            const int r = tid >> 2;
            const int cl = tid & 3;
            const int qg = q0 + r;
            const float4* qr = (const float4*)(Qs + r * ROWP);
            float sc[16];
#pragma unroll
            for (int jj = 0; jj < 16; jj++) sc[jj] = 0.f;
            for (int d = 0; d < 32; d++) {
                float4 a = qr[d];
#pragma unroll
                for (int jj = 0; jj < 16; jj++) {
                    float4 b = *(const float4*)(Ks + (cl + jj * 4) * ROWP + d * 4);
                    sc[jj] += a.x * b.x + a.y * b.y + a.z * b.z + a.w * b.w;
                }
            }
#pragma unroll
            for (int jj = 0; jj < 16; jj++) {
                int c = cl + jj * 4;
                Ss[r * SSP + c] = (k0 + c <= qg) ? sc[jj] * scale : -1e30f;
            }
        }
        __syncthreads();

        float mnew = m;
#pragma unroll
        for (int c = 0; c < KT; c++) mnew = fmaxf(mnew, Ss[qi * SSP + c]);
        float corr = __expf(m - mnew);
        l *= corr;
#pragma unroll
        for (int i = 0; i < 8; i++) {
            acc4[i].x *= corr; acc4[i].y *= corr;
            acc4[i].z *= corr; acc4[i].w *= corr;
        }
        for (int c = 0; c < KT; c++) {
            float p = __expf(Ss[qi * SSP + c] - mnew);
            l += p;
            const float4* vrow = (const float4*)(Vs + c * ROWP);
#pragma unroll
            for (int i = 0; i < 8; i++) {
                float4 v = vrow[dgrp + 4 * i];   // dims dgrp*4 + i*16 (bank-clean)
                acc4[i].x += p * v.x; acc4[i].y += p * v.y;
                acc4[i].z += p * v.z; acc4[i].w += p * v.w;
            }
        }
        m = mnew;
        __syncthreads();
    }

    // fp16 packed-tile epilogue
    float inv = 1.f / l;
    const int s = q0 + qi;
    const int rowblk = s >> 7, rin = s & 127;
#pragma unroll
    for (int i = 0; i < 8; i++) {
        int dim_off = dgrp * 4 + i * 16;             // within head
        int gdim = h * HD + dim_off;
        int chunk = gdim >> 6;
        int c2 = (gdim & 63) >> 1;                   // even
        __half2 lo = __floats2half2_rn(acc4[i].x * inv, acc4[i].y * inv);
        __half2 hi = __floats2half2_rn(acc4[i].z * inv, acc4[i].w * inv);
        uint32_t* dst = &O[((size_t)rowblk * 64 + chunk) * TILE_U32 + SWZ(rin, c2)];
        *(uint2*)dst = make_uint2(*(uint32_t*)&lo, *(uint32_t*)&hi);
    }
}

// ---------------------------------------------------------------------------
// Host launcher (ordered so the 4th launch = Q-projection GEMM for ncu)
// ---------------------------------------------------------------------------
extern "C" void kernel_launch(void* const* d_in, const int* in_sizes, int n_in,
                              void* d_out, int out_size) {
    const float* x  = (const float*)d_in[0];
    const float* fc = (const float*)d_in[1];
    const float* fs = (const float*)d_in[2];
    const float* wq = (const float*)d_in[4];
    const float* wk = (const float*)d_in[5];
    const float* wv = (const float*)d_in[6];
    const float* wo = (const float*)d_in[7];
    float* out = (float*)d_out;

    float *qp, *kp, *vp;
    uint32_t *ap, *xp, *wqT, *wkT, *wvT, *woT;
    cudaGetSymbolAddress((void**)&qp, g_q);
    cudaGetSymbolAddress((void**)&kp, g_k);
    cudaGetSymbolAddress((void**)&vp, g_v);
    cudaGetSymbolAddress((void**)&ap, g_attn);
    cudaGetSymbolAddress((void**)&xp, g_xp);
    cudaGetSymbolAddress((void**)&wqT, g_wqT);
    cudaGetSymbolAddress((void**)&wkT, g_wkT);
    cudaGetSymbolAddress((void**)&wvT, g_wvT);
    cudaGetSymbolAddress((void**)&woT, g_woT);

    cudaFuncSetAttribute(mma_gemm, cudaFuncAttributeMaxDynamicSharedMemorySize, GEMM_SMEM);

    // 1-3: prep for Q gemm
    transpose_pack_kernel<<<dim3(4096 / 32, 4096 / 32), dim3(32, 8)>>>(wq, wqT, 4096, 4096);
    {
        int n4 = S_LEN * D_MODEL / 4;
        pack_x_kernel<<<(n4 + 255) / 256, 256>>>(x, xp, D_MODEL);
    }
    transpose_pack_kernel<<<dim3(1024 / 32, 4096 / 32), dim3(32, 8)>>>(wk, wkT, 4096, 1024);

    // 4: Q projection (ncu-captured launch)
    mma_gemm<<<dim3(4096 / 128, S_LEN / 128), 256, GEMM_SMEM>>>(xp, wqT, qp, S_LEN, 4096, 4096);

    // 5-8: remaining prep + K/V projections
    transpose_pack_kernel<<<dim3(1024 / 32, 4096 / 32), dim3(32, 8)>>>(wv, wvT, 4096, 1024);
    mma_gemm<<<dim3(1024 / 128, S_LEN / 128), 256, GEMM_SMEM>>>(xp, wkT, kp, S_LEN, 1024, 4096);
    mma_gemm<<<dim3(1024 / 128, S_LEN / 128), 256, GEMM_SMEM>>>(xp, wvT, vp, S_LEN, 1024, 4096);
    transpose_pack_kernel<<<dim3(4096 / 32, 4096 / 32), dim3(32, 8)>>>(wo, woT, 4096, 4096);

    // RoPE
    {
        int tq = S_LEN * N_HEADS * (HD / 2);
        rope_kernel<<<(tq + 255) / 256, 256>>>(qp, fc, fs, N_HEADS);
        int tk = S_LEN * N_KV * (HD / 2);
        rope_kernel<<<(tk + 255) / 256, 256>>>(kp, fc, fs, N_KV);
    }

    // Attention (writes fp16 packed g_attn)
    {
        int smem_bytes = (3 * QT * ROWP + QT * SSP) * (int)sizeof(float);
        cudaFuncSetAttribute(attn_kernel, cudaFuncAttributeMaxDynamicSharedMemorySize,
                             smem_bytes);
        attn_kernel<<<dim3(S_LEN / QT, N_HEADS), 256, smem_bytes>>>(qp, kp, vp, ap);
    }

    // Output projection
    mma_gemm<<<dim3(4096 / 128, S_LEN / 128), 256, GEMM_SMEM>>>(ap, woT, out, S_LEN, 4096, 4096);
}

// round 6
// speedup vs baseline: 18.6668x; 3.8896x over previous
#include <cuda_runtime.h>
#include <cuda_fp16.h>
#include <cstdint>

// Shapes (fixed)
#define S_LEN 2048
#define D_MODEL 4096
#define N_HEADS 32
#define N_KV 8
#define HD 128

// Scratch (allocation-free rule: device globals)
__device__ float    g_q[S_LEN * N_HEADS * HD];          // fp32 Q (post-rope)
__device__ float    g_k[S_LEN * N_KV * HD];             // fp32 K (pre-rope)
__device__ float    g_v[S_LEN * N_KV * HD];             // fp32 V
__device__ uint32_t g_attn[S_LEN * N_HEADS * HD / 2];   // fp16 packed tiles
__device__ uint32_t g_xp[S_LEN * D_MODEL / 2];          // fp16 packed x
__device__ uint32_t g_wqT[4096 * 4096 / 2];
__device__ uint32_t g_wkT[1024 * 4096 / 2];
__device__ uint32_t g_wvT[1024 * 4096 / 2];
__device__ uint32_t g_woT[4096 * 4096 / 2];
__device__ uint32_t g_khl[8 * 32 * 8192];               // K hi+lo fp16 tiles (8 MB)
__device__ uint32_t g_vt[8 * 32 * 4096];                // V^T fp16 tiles (4 MB)

// GEMM packed tile: [rowblk(128)][chunk(64 k)][128 x 32 half2], swizzled
#define SWZ(r, c2) (((r) << 5) + ((c2) ^ (((r) & 7) << 2)))
#define TILE_U32 4096
#define TILE_B 16384
// Attention K tile: [64 r][64 half2]; V^T tile: [128 d][32 half2]
#define KSWZ(r, c2) (((r) << 6) + ((c2) ^ (((r) & 7) << 2)))
#define VSWZ(r, c2) (((r) << 5) + ((c2) ^ (((r) & 7) << 2)))

// ---------------------------------------------------------------------------
// Helpers (baseline PTX only)
// ---------------------------------------------------------------------------
__device__ __forceinline__ uint32_t smem_u32(const void* p) {
    uint32_t a;
    asm("{ .reg .u64 t; cvta.to.shared.u64 t, %1; cvt.u32.u64 %0, t; }" : "=r"(a) : "l"(p));
    return a;
}
#define MBARRIER_INIT(mbar, cnt) \
    asm volatile("mbarrier.init.shared.b64 [%0], %1;" :: "r"((uint32_t)(mbar)), "r"((uint32_t)(cnt)) : "memory")
#define MBARRIER_EXPECT_TX(mbar, bytes) \
    asm volatile("mbarrier.arrive.expect_tx.shared.b64 _, [%0], %1;" :: "r"((uint32_t)(mbar)), "r"((uint32_t)(bytes)) : "memory")
#define MBARRIER_WAIT_PARITY(mbar, par) do {                                        \
    uint32_t _m = (uint32_t)(mbar); uint32_t _p = (uint32_t)(par); uint32_t _d;     \
    asm volatile("{\n\t.reg .pred p;\n\t"                                           \
        "mbarrier.try_wait.parity.acquire.cta.shared::cta.b64 p, [%1], %2;\n\t"     \
        "selp.b32 %0, 1, 0, p;\n\t}" : "=r"(_d) : "r"(_m), "r"(_p) : "memory");     \
    if (!_d) {                                                                      \
        asm volatile("{\n\t.reg .pred P1;\n\t"                                      \
            "WL_%=:\n\t"                                                            \
            "mbarrier.try_wait.parity.acquire.cta.shared::cta.b64 P1, [%0], %1, 0x989680;\n\t" \
            "@P1 bra.uni WD_%=;\n\t"                                                \
            "bra.uni WL_%=;\n\t"                                                    \
            "WD_%=:\n\t}" :: "r"(_m), "r"(_p) : "memory");                          \
    }                                                                               \
} while (0)

__device__ __forceinline__ void bulk_g2s(uint32_t dst, const void* src,
                                         uint32_t bytes, uint32_t mbar) {
    asm volatile(
        "cp.async.bulk.shared::cluster.global.mbarrier::complete_tx::bytes [%0], [%1], %2, [%3];"
        :: "r"(dst), "l"(src), "r"(bytes), "r"(mbar) : "memory");
}

__device__ __forceinline__ void mma16816(float* d, const uint32_t* a, const uint32_t* b) {
    asm volatile(
        "mma.sync.aligned.m16n8k16.row.col.f32.f16.f16.f32 "
        "{%0,%1,%2,%3}, {%4,%5,%6,%7}, {%8,%9}, {%0,%1,%2,%3};"
        : "+f"(d[0]), "+f"(d[1]), "+f"(d[2]), "+f"(d[3])
        : "r"(a[0]), "r"(a[1]), "r"(a[2]), "r"(a[3]), "r"(b[0]), "r"(b[1]));
}

__device__ __forceinline__ void split2(float x, float y,
                                       uint32_t& hi, uint32_t& lo) {
    __half hx = __float2half_rn(x), hy = __float2half_rn(y);
    __half lx = __float2half_rn(x - __half2float(hx));
    __half ly = __float2half_rn(y - __half2float(hy));
    __half2 H = __halves2half2(hx, hy), L = __halves2half2(lx, ly);
    hi = *(uint32_t*)&H; lo = *(uint32_t*)&L;
}

// ---------------------------------------------------------------------------
// fp16 mma.sync GEMM on packed-tile operands (C = A @ B^T, fp32 out).
// ---------------------------------------------------------------------------
#define STAGE_B (2 * TILE_B)
#define NSTG 3
#define GEMM_SMEM (1024 + NSTG * STAGE_B)

__global__ __launch_bounds__(256, 2)
void mma_gemm(const uint32_t* __restrict__ Ap, const uint32_t* __restrict__ Bp,
              float* __restrict__ C, int M, int N, int K) {
    extern __shared__ char smem[];
    const uint32_t sb = smem_u32(smem);
    const int tid = threadIdx.x;
    const int wid = tid >> 5, lane = tid & 31;
    const int wm = wid & 3;
    const int wn = wid >> 2;
    const int mlane = lane >> 2;
    const int klane = lane & 3;
    const int nch = K >> 6;

    if (tid == 0) {
#pragma unroll
        for (int s = 0; s < NSTG; s++) MBARRIER_INIT(sb + 8 * s, 1);
    }
    __syncthreads();

    const uint32_t* Abase = Ap + (size_t)blockIdx.y * nch * TILE_U32;
    const uint32_t* Bbase = Bp + (size_t)blockIdx.x * nch * TILE_U32;

    auto issue = [&](int chunk, int st) {
        uint32_t base = sb + 1024 + st * STAGE_B;
        MBARRIER_EXPECT_TX(sb + 8 * st, STAGE_B);
        bulk_g2s(base, Abase + (size_t)chunk * TILE_U32, TILE_B, sb + 8 * st);
        bulk_g2s(base + TILE_B, Bbase + (size_t)chunk * TILE_U32, TILE_B, sb + 8 * st);
    };

    if (tid == 0) { issue(0, 0); issue(1, 1); }

    float acc[2][8][4];
#pragma unroll
    for (int mi = 0; mi < 2; mi++)
#pragma unroll
        for (int ni = 0; ni < 8; ni++)
#pragma unroll
            for (int j = 0; j < 4; j++) acc[mi][ni][j] = 0.f;

    int cst = 0, cph = 0;
    int pk = 2, pst = 2;

    for (int it = 0; it < nch; it++) {
        __syncthreads();
        if (pk < nch) {
            if (tid == 0) issue(pk, pst);
            pk++; pst++; if (pst == NSTG) pst = 0;
        }
        MBARRIER_WAIT_PARITY(sb + 8 * cst, cph);

        const uint32_t* As = (const uint32_t*)(smem + 1024 + cst * STAGE_B);
        const uint32_t* Bs = As + TILE_U32;

#pragma unroll
        for (int s = 0; s < 4; s++) {
            const int c2b = s * 8;
            uint32_t a[2][4], b[8][2];
#pragma unroll
            for (int mi = 0; mi < 2; mi++) {
                int r = wm * 32 + mi * 16 + mlane;
                a[mi][0] = As[SWZ(r, c2b + klane)];
                a[mi][1] = As[SWZ(r + 8, c2b + klane)];
                a[mi][2] = As[SWZ(r, c2b + klane + 4)];
                a[mi][3] = As[SWZ(r + 8, c2b + klane + 4)];
            }
#pragma unroll
            for (int ni = 0; ni < 8; ni++) {
                int rb = wn * 64 + ni * 8 + mlane;
                b[ni][0] = Bs[SWZ(rb, c2b + klane)];
                b[ni][1] = Bs[SWZ(rb, c2b + klane + 4)];
            }
#pragma unroll
            for (int mi = 0; mi < 2; mi++)
#pragma unroll
                for (int ni = 0; ni < 8; ni++)
                    mma16816(acc[mi][ni], a[mi], b[ni]);
        }

        cst++; if (cst == NSTG) { cst = 0; cph ^= 1; }
    }

    const int row0 = blockIdx.y * 128;
    const int col0 = blockIdx.x * 128;
#pragma unroll
    for (int mi = 0; mi < 2; mi++) {
        int row = row0 + wm * 32 + mi * 16 + mlane;
#pragma unroll
        for (int ni = 0; ni < 8; ni++) {
            int col = col0 + wn * 64 + ni * 8 + 2 * klane;
            *(float2*)&C[(size_t)row * N + col] =
                make_float2(acc[mi][ni][0], acc[mi][ni][1]);
            *(float2*)&C[(size_t)(row + 8) * N + col] =
                make_float2(acc[mi][ni][2], acc[mi][ni][3]);
        }
    }
}

// ---------------------------------------------------------------------------
// Transpose + fp16 + pack weights
// ---------------------------------------------------------------------------
__global__ void transpose_pack_kernel(const float* __restrict__ W, uint32_t* __restrict__ P,
                                      int R, int C) {
    __shared__ float t[32][33];
    int bx = blockIdx.x * 32;
    int by = blockIdx.y * 32;
    int tx = threadIdx.x, ty = threadIdx.y;
#pragma unroll
    for (int i = 0; i < 32; i += 8)
        t[ty + i][tx] = W[(size_t)(by + ty + i) * C + bx + tx];
    __syncthreads();
    const int nch = R >> 6;
    const int kk2 = tx & 15;
    const int kglob = by + 2 * kk2;
    const int chunk = kglob >> 6;
    const int c2 = (kglob & 63) >> 1;
    const int nbase = (tx >> 4) * 8 + ty;
#pragma unroll
    for (int g = 0; g < 2; g++) {
        int nloc = nbase + g * 16;
        int n = bx + nloc;
        int colblk = n >> 7, r = n & 127;
        __half2 v = __floats2half2_rn(t[2 * kk2][nloc], t[2 * kk2 + 1][nloc]);
        P[((size_t)colblk * nch + chunk) * TILE_U32 + SWZ(r, c2)] = *(uint32_t*)&v;
    }
}

// ---------------------------------------------------------------------------
// fp16 + pack activations
// ---------------------------------------------------------------------------
__global__ void pack_x_kernel(const float* __restrict__ X, uint32_t* __restrict__ P, int K) {
    int idx = blockIdx.x * blockDim.x + threadIdx.x;
    int perrow = K >> 2;
    int s = idx / perrow;
    int d4 = (idx % perrow) << 2;
    float4 v = *(const float4*)&X[(size_t)s * K + d4];
    int rowblk = s >> 7, r = s & 127;
    int chunk = d4 >> 6;
    int c2 = (d4 & 63) >> 1;
    int nch = K >> 6;
    __half2 lo = __floats2half2_rn(v.x, v.y);
    __half2 hi = __floats2half2_rn(v.z, v.w);
    uint32_t* dst = &P[((size_t)rowblk * nch + chunk) * TILE_U32 + SWZ(r, c2)];
    *(uint2*)dst = make_uint2(*(uint32_t*)&lo, *(uint32_t*)&hi);
}

// ---------------------------------------------------------------------------
// RoPE in-place (fp32) for Q
// ---------------------------------------------------------------------------
__global__ void rope_kernel(float* __restrict__ t,
                            const float* __restrict__ cosb,
                            const float* __restrict__ sinb, int Hn) {
    int idx = blockIdx.x * blockDim.x + threadIdx.x;
    int total = S_LEN * Hn * (HD / 2);
    if (idx >= total) return;
    int i = idx & 63;
    int h = (idx >> 6) % Hn;
    int s = idx / (64 * Hn);
    float c = cosb[s * 64 + i];
    float sn = sinb[s * 64 + i];
    float* p = t + ((size_t)(s * Hn + h) * HD) + 2 * i;
    float a = p[0], b = p[1];
    p[0] = a * c - b * sn;
    p[1] = a * sn + b * c;
}

// ---------------------------------------------------------------------------
// RoPE + hi/lo fp16 split + pack K into attention tiles
// ---------------------------------------------------------------------------
__global__ void rope_pack_k(const float* __restrict__ K,
                            const float* __restrict__ cosb,
                            const float* __restrict__ sinb,
                            uint32_t* __restrict__ P) {
    int idx = blockIdx.x * blockDim.x + threadIdx.x;
    if (idx >= S_LEN * N_KV * 64) return;
    int i = idx & 63;
    int kv = (idx >> 6) & 7;
    int s = idx >> 9;
    float c = cosb[s * 64 + i], sn = sinb[s * 64 + i];
    float2 v = *(const float2*)&K[((size_t)s * N_KV + kv) * HD + 2 * i];
    float a = v.x * c - v.y * sn;
    float b = v.x * sn + v.y * c;
    uint32_t hi, lo;
    split2(a, b, hi, lo);
    int t = kv * 32 + (s >> 6);
    int r = s & 63;
    size_t off = (size_t)t * 8192 + KSWZ(r, i);
    P[off] = hi;
    P[off + 4096] = lo;
}

// ---------------------------------------------------------------------------
// Pack V^T fp16 tiles: [kv][s-chunk][d=128][s-in-chunk half2 swizzled]
// ---------------------------------------------------------------------------
__global__ void pack_vt(const float* __restrict__ V, uint32_t* __restrict__ P) {
    __shared__ float t[64][33];
    int c = blockIdx.x;       // s-chunk
    int kv = blockIdx.y;
    int dg = blockIdx.z;      // d-group of 32
    int tx = threadIdx.x, ty = threadIdx.y;   // 32 x 8
    int s0 = c * 64, d0 = dg * 32;
#pragma unroll
    for (int ss = ty; ss < 64; ss += 8)
        t[ss][tx] = V[((size_t)(s0 + ss) * N_KV + kv) * HD + d0 + tx];
    __syncthreads();
    int tile = kv * 32 + c;
    int r = d0 + tx;
#pragma unroll
    for (int jj = ty; jj < 32; jj += 8) {
        __half2 v = __floats2half2_rn(t[2 * jj][tx], t[2 * jj + 1][tx]);
        P[(size_t)tile * 4096 + VSWZ(r, jj)] = *(uint32_t*)&v;
    }
}

// ---------------------------------------------------------------------------
// Tensor-core flash attention (causal). 1 CTA = 64 queries x 1 head.
// S = qh*kh + ql*kh + qh*kl (hi/lo split); PV in plain fp16.
// ---------------------------------------------------------------------------
#define FA_STAGE 49152                     // 32KB K(hi+lo) + 16KB Vt
#define FA_SMEM (1024 + 2 * FA_STAGE)      // 99328

__global__ __launch_bounds__(128, 2)
void fa_kernel(const float* __restrict__ Q, const uint32_t* __restrict__ Kp,
               const uint32_t* __restrict__ Vp, uint32_t* __restrict__ O) {
    extern __shared__ char smem[];
    const uint32_t sb = smem_u32(smem);
    const int tid = threadIdx.x;
    const int w = tid >> 5, lane = tid & 31;
    const int h = blockIdx.y;
    const int kvh = h >> 2;
    const int qblk = blockIdx.x;
    const int q0 = qblk * 64;

    if (tid == 0) { MBARRIER_INIT(sb + 0, 1); MBARRIER_INIT(sb + 8, 1); }
    __syncthreads();

    // Q fragments (hi/lo split, scale folded in)
    const float scale = 0.08838834764831845f;
    const int rq = q0 + w * 16 + (lane >> 2);
    const float* Qr0 = Q + ((size_t)rq * N_HEADS + h) * HD;
    const float* Qr1 = Q + ((size_t)(rq + 8) * N_HEADS + h) * HD;
    uint32_t qh[8][4], ql[8][4];
#pragma unroll
    for (int kk = 0; kk < 8; kk++) {
        int d0 = kk * 16 + 2 * (lane & 3);
        float2 v00 = *(const float2*)(Qr0 + d0);
        float2 v10 = *(const float2*)(Qr1 + d0);
        float2 v01 = *(const float2*)(Qr0 + d0 + 8);
        float2 v11 = *(const float2*)(Qr1 + d0 + 8);
        split2(v00.x * scale, v00.y * scale, qh[kk][0], ql[kk][0]);
        split2(v10.x * scale, v10.y * scale, qh[kk][1], ql[kk][1]);
        split2(v01.x * scale, v01.y * scale, qh[kk][2], ql[kk][2]);
        split2(v11.x * scale, v11.y * scale, qh[kk][3], ql[kk][3]);
    }

    const int nc = qblk + 1;
    const uint32_t* Kt = Kp + (size_t)(kvh * 32) * 8192;
    const uint32_t* Vt = Vp + (size_t)(kvh * 32) * 4096;

    auto issue = [&](int c) {
        int st = c & 1;
        uint32_t base = sb + 1024 + st * FA_STAGE;
        MBARRIER_EXPECT_TX(sb + 8 * st, FA_STAGE);
        bulk_g2s(base, Kt + (size_t)c * 8192, 32768, sb + 8 * st);
        bulk_g2s(base + 32768, Vt + (size_t)c * 4096, 16384, sb + 8 * st);
    };
    if (tid == 0) { issue(0); if (nc > 1) issue(1); }

    float m0 = -1e30f, m1 = -1e30f, l0 = 0.f, l1 = 0.f;
    float oacc[16][4];
#pragma unroll
    for (int i = 0; i < 16; i++)
#pragma unroll
        for (int j = 0; j < 4; j++) oacc[i][j] = 0.f;

    int ph0 = 0, ph1 = 0;

    for (int c = 0; c < nc; c++) {
        const int st = c & 1;
        if (st == 0) { MBARRIER_WAIT_PARITY(sb + 0, ph0); ph0 ^= 1; }
        else         { MBARRIER_WAIT_PARITY(sb + 8, ph1); ph1 ^= 1; }

        const uint32_t* Kh = (const uint32_t*)(smem + 1024 + st * FA_STAGE);
        const uint32_t* Kl = Kh + 4096;
        const uint32_t* Vs = Kh + 8192;

        // S = Q K^T (3-pass split)
        float sacc[8][4];
#pragma unroll
        for (int nt = 0; nt < 8; nt++) {
#pragma unroll
            for (int j = 0; j < 4; j++) sacc[nt][j] = 0.f;
            const int r = nt * 8 + (lane >> 2);
#pragma unroll
            for (int kk = 0; kk < 8; kk++) {
                int c2 = kk * 8 + (lane & 3);
                uint32_t bh[2] = { Kh[KSWZ(r, c2)], Kh[KSWZ(r, c2 + 4)] };
                uint32_t bl[2] = { Kl[KSWZ(r, c2)], Kl[KSWZ(r, c2 + 4)] };
                mma16816(sacc[nt], qh[kk], bh);
                mma16816(sacc[nt], ql[kk], bh);
                mma16816(sacc[nt], qh[kk], bl);
            }
        }

        // causal mask on diagonal chunk
        if (c == qblk) {
#pragma unroll
            for (int nt = 0; nt < 8; nt++) {
                int cg = c * 64 + nt * 8 + 2 * (lane & 3);
                if (cg > rq)          sacc[nt][0] = -1e30f;
                if (cg + 1 > rq)      sacc[nt][1] = -1e30f;
                if (cg > rq + 8)      sacc[nt][2] = -1e30f;
                if (cg + 1 > rq + 8)  sacc[nt][3] = -1e30f;
            }
        }

        // online softmax
        float mx0 = -1e30f, mx1 = -1e30f;
#pragma unroll
        for (int nt = 0; nt < 8; nt++) {
            mx0 = fmaxf(mx0, fmaxf(sacc[nt][0], sacc[nt][1]));
            mx1 = fmaxf(mx1, fmaxf(sacc[nt][2], sacc[nt][3]));
        }
        mx0 = fmaxf(mx0, __shfl_xor_sync(0xffffffff, mx0, 1));
        mx0 = fmaxf(mx0, __shfl_xor_sync(0xffffffff, mx0, 2));
        mx1 = fmaxf(mx1, __shfl_xor_sync(0xffffffff, mx1, 1));
        mx1 = fmaxf(mx1, __shfl_xor_sync(0xffffffff, mx1, 2));
        float mn0 = fmaxf(m0, mx0), mn1 = fmaxf(m1, mx1);
        float cor0 = __expf(m0 - mn0), cor1 = __expf(m1 - mn1);
        l0 *= cor0; l1 *= cor1;
#pragma unroll
        for (int i = 0; i < 16; i++) {
            oacc[i][0] *= cor0; oacc[i][1] *= cor0;
            oacc[i][2] *= cor1; oacc[i][3] *= cor1;
        }
        float rs0 = 0.f, rs1 = 0.f;
        uint32_t pf[4][4];
#pragma unroll
        for (int nt = 0; nt < 8; nt++) {
            float p0 = __expf(sacc[nt][0] - mn0);
            float p1 = __expf(sacc[nt][1] - mn0);
            float p2 = __expf(sacc[nt][2] - mn1);
            float p3 = __expf(sacc[nt][3] - mn1);
            rs0 += p0 + p1; rs1 += p2 + p3;
            __half2 h01 = __floats2half2_rn(p0, p1);
            __half2 h23 = __floats2half2_rn(p2, p3);
            int kt = nt >> 1, hi = (nt & 1) << 1;
            pf[kt][hi]     = *(uint32_t*)&h01;
            pf[kt][hi + 1] = *(uint32_t*)&h23;
        }
        rs0 += __shfl_xor_sync(0xffffffff, rs0, 1);
        rs0 += __shfl_xor_sync(0xffffffff, rs0, 2);
        rs1 += __shfl_xor_sync(0xffffffff, rs1, 1);
        rs1 += __shfl_xor_sync(0xffffffff, rs1, 2);
        l0 += rs0; l1 += rs1;
        m0 = mn0; m1 = mn1;

        // O += P V
#pragma unroll
        for (int nt2 = 0; nt2 < 16; nt2++) {
            const int r = nt2 * 8 + (lane >> 2);
#pragma unroll
            for (int kt = 0; kt < 4; kt++) {
                int c2v = kt * 8 + (lane & 3);
                uint32_t b[2] = { Vs[VSWZ(r, c2v)], Vs[VSWZ(r, c2v + 4)] };
                mma16816(oacc[nt2], pf[kt], b);
            }
        }

        __syncthreads();
        if (tid == 0 && c + 2 < nc) issue(c + 2);
    }

    // Epilogue: fp16 packed-tile output for W_o GEMM
    float i0 = 1.f / l0, i1 = 1.f / l1;
    const int s0r = rq, s1r = rq + 8;
    const int rb0 = s0r >> 7, ri0 = s0r & 127;
    const int rb1 = s1r >> 7, ri1 = s1r & 127;
#pragma unroll
    for (int nt2 = 0; nt2 < 16; nt2++) {
        int d = nt2 * 8 + 2 * (lane & 3);
        int gdim = h * HD + d;
        int chunk = gdim >> 6;
        int c2 = (gdim & 63) >> 1;
        __half2 vlo = __floats2half2_rn(oacc[nt2][0] * i0, oacc[nt2][1] * i0);
        __half2 vhi = __floats2half2_rn(oacc[nt2][2] * i1, oacc[nt2][3] * i1);
        O[((size_t)rb0 * 64 + chunk) * TILE_U32 + SWZ(ri0, c2)] = *(uint32_t*)&vlo;
        O[((size_t)rb1 * 64 + chunk) * TILE_U32 + SWZ(ri1, c2)] = *(uint32_t*)&vhi;
    }
}

// ---------------------------------------------------------------------------
// Host launcher
// ---------------------------------------------------------------------------
extern "C" void kernel_launch(void* const* d_in, const int* in_sizes, int n_in,
                              void* d_out, int out_size) {
    const float* x  = (const float*)d_in[0];
    const float* fc = (const float*)d_in[1];
    const float* fs = (const float*)d_in[2];
    const float* wq = (const float*)d_in[4];
    const float* wk = (const float*)d_in[5];
    const float* wv = (const float*)d_in[6];
    const float* wo = (const float*)d_in[7];
    float* out = (float*)d_out;

    float *qp, *kp, *vp;
    uint32_t *ap, *xp, *wqT, *wkT, *wvT, *woT, *khl, *vt;
    cudaGetSymbolAddress((void**)&qp, g_q);
    cudaGetSymbolAddress((void**)&kp, g_k);
    cudaGetSymbolAddress((void**)&vp, g_v);
    cudaGetSymbolAddress((void**)&ap, g_attn);
    cudaGetSymbolAddress((void**)&xp, g_xp);
    cudaGetSymbolAddress((void**)&wqT, g_wqT);
    cudaGetSymbolAddress((void**)&wkT, g_wkT);
    cudaGetSymbolAddress((void**)&wvT, g_wvT);
    cudaGetSymbolAddress((void**)&woT, g_woT);
    cudaGetSymbolAddress((void**)&khl, g_khl);
    cudaGetSymbolAddress((void**)&vt, g_vt);

    cudaFuncSetAttribute(mma_gemm, cudaFuncAttributeMaxDynamicSharedMemorySize, GEMM_SMEM);
    cudaFuncSetAttribute(fa_kernel, cudaFuncAttributeMaxDynamicSharedMemorySize, FA_SMEM);

    // Prep + projections
    transpose_pack_kernel<<<dim3(4096 / 32, 4096 / 32), dim3(32, 8)>>>(wq, wqT, 4096, 4096);
    {
        int n4 = S_LEN * D_MODEL / 4;
        pack_x_kernel<<<(n4 + 255) / 256, 256>>>(x, xp, D_MODEL);
    }
    transpose_pack_kernel<<<dim3(1024 / 32, 4096 / 32), dim3(32, 8)>>>(wk, wkT, 4096, 1024);
    mma_gemm<<<dim3(4096 / 128, S_LEN / 128), 256, GEMM_SMEM>>>(xp, wqT, qp, S_LEN, 4096, 4096);
    transpose_pack_kernel<<<dim3(1024 / 32, 4096 / 32), dim3(32, 8)>>>(wv, wvT, 4096, 1024);
    mma_gemm<<<dim3(1024 / 128, S_LEN / 128), 256, GEMM_SMEM>>>(xp, wkT, kp, S_LEN, 1024, 4096);
    mma_gemm<<<dim3(1024 / 128, S_LEN / 128), 256, GEMM_SMEM>>>(xp, wvT, vp, S_LEN, 1024, 4096);
    transpose_pack_kernel<<<dim3(4096 / 32, 4096 / 32), dim3(32, 8)>>>(wo, woT, 4096, 4096);

    // RoPE(Q) fp32; RoPE(K)+split-pack; V^T pack
    {
        int tq = S_LEN * N_HEADS * (HD / 2);
        rope_kernel<<<(tq + 255) / 256, 256>>>(qp, fc, fs, N_HEADS);
        int tk = S_LEN * N_KV * 64;
        rope_pack_k<<<(tk + 255) / 256, 256>>>(kp, fc, fs, khl);
        pack_vt<<<dim3(32, 8, 4), dim3(32, 8)>>>(vp, vt);
    }

    // Flash attention (tensor cores)
    fa_kernel<<<dim3(S_LEN / 64, N_HEADS), 128, FA_SMEM>>>(qp, khl, vt, ap);

    // Output projection
    mma_gemm<<<dim3(4096 / 128, S_LEN / 128), 256, GEMM_SMEM>>>(ap, woT, out, S_LEN, 4096, 4096);
}

// round 7
// speedup vs baseline: 20.2032x; 1.0823x over previous
#include <cuda_runtime.h>
#include <cuda_fp16.h>
#include <cstdint>

// Shapes (fixed)
#define S_LEN 2048
#define D_MODEL 4096
#define N_HEADS 32
#define N_KV 8
#define HD 128

// Scratch (allocation-free rule: device globals)
__device__ float    g_q[S_LEN * N_HEADS * HD];          // fp32 Q (rope'd)
__device__ float    g_v[S_LEN * N_KV * HD];             // fp32 V
__device__ uint32_t g_attn[S_LEN * N_HEADS * HD / 2];   // fp16 packed tiles
__device__ uint32_t g_xp[S_LEN * D_MODEL / 2];          // fp16 packed x
__device__ uint32_t g_wqkv[48 * 64 * 4096];             // packed [wq|wk|wv]
__device__ uint32_t g_woT[4096 * 4096 / 2];
__device__ uint32_t g_khl[8 * 32 * 8192];               // K hi+lo fp16 tiles
__device__ uint32_t g_vt[8 * 32 * 4096];                // V^T fp16 tiles

// GEMM packed tile: [rowblk(128)][chunk(64 k)][128 x 32 half2], swizzled
#define SWZ(r, c2) (((r) << 5) + ((c2) ^ (((r) & 7) << 2)))
#define TILE_U32 4096
#define TILE_B 16384
// Attention K tile: [64 r][64 half2]; V^T tile: [128 d][32 half2]
#define KSWZ(r, c2) (((r) << 6) + ((c2) ^ (((r) & 7) << 2)))
#define VSWZ(r, c2) (((r) << 5) + ((c2) ^ (((r) & 7) << 2)))

// ---------------------------------------------------------------------------
// Helpers (baseline PTX only)
// ---------------------------------------------------------------------------
__device__ __forceinline__ uint32_t smem_u32(const void* p) {
    uint32_t a;
    asm("{ .reg .u64 t; cvta.to.shared.u64 t, %1; cvt.u32.u64 %0, t; }" : "=r"(a) : "l"(p));
    return a;
}
#define MBARRIER_INIT(mbar, cnt) \
    asm volatile("mbarrier.init.shared.b64 [%0], %1;" :: "r"((uint32_t)(mbar)), "r"((uint32_t)(cnt)) : "memory")
#define MBARRIER_EXPECT_TX(mbar, bytes) \
    asm volatile("mbarrier.arrive.expect_tx.shared.b64 _, [%0], %1;" :: "r"((uint32_t)(mbar)), "r"((uint32_t)(bytes)) : "memory")
#define MBARRIER_WAIT_PARITY(mbar, par) do {                                        \
    uint32_t _m = (uint32_t)(mbar); uint32_t _p = (uint32_t)(par); uint32_t _d;     \
    asm volatile("{\n\t.reg .pred p;\n\t"                                           \
        "mbarrier.try_wait.parity.acquire.cta.shared::cta.b64 p, [%1], %2;\n\t"     \
        "selp.b32 %0, 1, 0, p;\n\t}" : "=r"(_d) : "r"(_m), "r"(_p) : "memory");     \
    if (!_d) {                                                                      \
        asm volatile("{\n\t.reg .pred P1;\n\t"                                      \
            "WL_%=:\n\t"                                                            \
            "mbarrier.try_wait.parity.acquire.cta.shared::cta.b64 P1, [%0], %1, 0x989680;\n\t" \
            "@P1 bra.uni WD_%=;\n\t"                                                \
            "bra.uni WL_%=;\n\t"                                                    \
            "WD_%=:\n\t}" :: "r"(_m), "r"(_p) : "memory");                          \
    }                                                                               \
} while (0)

__device__ __forceinline__ void bulk_g2s(uint32_t dst, const void* src,
                                         uint32_t bytes, uint32_t mbar) {
    asm volatile(
        "cp.async.bulk.shared::cluster.global.mbarrier::complete_tx::bytes [%0], [%1], %2, [%3];"
        :: "r"(dst), "l"(src), "r"(bytes), "r"(mbar) : "memory");
}

__device__ __forceinline__ void mma16816(float* d, const uint32_t* a, const uint32_t* b) {
    asm volatile(
        "mma.sync.aligned.m16n8k16.row.col.f32.f16.f16.f32 "
        "{%0,%1,%2,%3}, {%4,%5,%6,%7}, {%8,%9}, {%0,%1,%2,%3};"
        : "+f"(d[0]), "+f"(d[1]), "+f"(d[2]), "+f"(d[3])
        : "r"(a[0]), "r"(a[1]), "r"(a[2]), "r"(a[3]), "r"(b[0]), "r"(b[1]));
}

#define LDSM4(r0, r1, r2, r3, addr) \
    asm volatile("ldmatrix.sync.aligned.m8n8.x4.shared.b16 {%0,%1,%2,%3}, [%4];" \
                 : "=r"(r0), "=r"(r1), "=r"(r2), "=r"(r3) : "r"(addr))

__device__ __forceinline__ void split2(float x, float y,
                                       uint32_t& hi, uint32_t& lo) {
    __half hx = __float2half_rn(x), hy = __float2half_rn(y);
    __half lx = __float2half_rn(x - __half2float(hx));
    __half ly = __float2half_rn(y - __half2float(hy));
    __half2 H = __halves2half2(hx, hy), L = __halves2half2(lx, ly);
    hi = *(uint32_t*)&H; lo = *(uint32_t*)&L;
}

// ---------------------------------------------------------------------------
// fp16 mma.sync GEMM, ldmatrix-fed. mode 0: C += plain fp32 store.
// mode 1: QKV epilogue (Q rope fp32 / K rope+split pack / V fp32).
// ---------------------------------------------------------------------------
#define STAGE_B (2 * TILE_B)
#define NSTG 3
#define GEMM_SMEM (1024 + NSTG * STAGE_B)

__global__ __launch_bounds__(256, 2)
void mma_gemm(const uint32_t* __restrict__ Ap, const uint32_t* __restrict__ Bp,
              float* __restrict__ C, int M, int N, int K, int mode,
              const float* __restrict__ fc, const float* __restrict__ fs,
              float* __restrict__ Qo, uint32_t* __restrict__ Khl,
              float* __restrict__ Vo) {
    extern __shared__ char smem[];
    const uint32_t sb = smem_u32(smem);
    const int tid = threadIdx.x;
    const int wid = tid >> 5, lane = tid & 31;
    const int wm = wid & 3;
    const int wn = wid >> 2;
    const int mlane = lane >> 2;
    const int klane = lane & 3;
    const int lq = lane >> 3, lr = lane & 7;
    const int nch = K >> 6;

    if (tid == 0) {
#pragma unroll
        for (int s = 0; s < NSTG; s++) MBARRIER_INIT(sb + 8 * s, 1);
    }
    __syncthreads();

    const uint32_t* Abase = Ap + (size_t)blockIdx.y * nch * TILE_U32;
    const uint32_t* Bbase = Bp + (size_t)blockIdx.x * nch * TILE_U32;

    auto issue = [&](int chunk, int st) {
        uint32_t base = sb + 1024 + st * STAGE_B;
        MBARRIER_EXPECT_TX(sb + 8 * st, STAGE_B);
        bulk_g2s(base, Abase + (size_t)chunk * TILE_U32, TILE_B, sb + 8 * st);
        bulk_g2s(base + TILE_B, Bbase + (size_t)chunk * TILE_U32, TILE_B, sb + 8 * st);
    };

    if (tid == 0) { issue(0, 0); issue(1, 1); }

    float acc[2][8][4];
#pragma unroll
    for (int mi = 0; mi < 2; mi++)
#pragma unroll
        for (int ni = 0; ni < 8; ni++)
#pragma unroll
            for (int j = 0; j < 4; j++) acc[mi][ni][j] = 0.f;

    // ldmatrix lane rows (constant across chunks)
    const int ar0 = wm * 32 + (lq & 1) * 8 + lr;          // mi=0 a row
    const int ac4 = (lq >> 1) * 4;                        // a c2grp offset
    const int br_ = wn * 64 + (lq >> 1) * 8 + lr;         // b row base (j adds 16j)
    const int bc4 = (lq & 1) * 4;                         // b c2grp offset

    int cst = 0, cph = 0;
    int pk = 2, pst = 2;

    for (int it = 0; it < nch; it++) {
        __syncthreads();
        if (pk < nch) {
            if (tid == 0) issue(pk, pst);
            pk++; pst++; if (pst == NSTG) pst = 0;
        }
        MBARRIER_WAIT_PARITY(sb + 8 * cst, cph);

        const uint32_t Aadr = sb + 1024 + cst * STAGE_B;
        const uint32_t Badr = Aadr + TILE_B;

#pragma unroll
        for (int s = 0; s < 4; s++) {
            const int c2b = s * 8;
            uint32_t a[2][4];
            LDSM4(a[0][0], a[0][1], a[0][2], a[0][3],
                  Aadr + 4 * SWZ(ar0, c2b + ac4));
            LDSM4(a[1][0], a[1][1], a[1][2], a[1][3],
                  Aadr + 4 * SWZ(ar0 + 16, c2b + ac4));
#pragma unroll
            for (int j = 0; j < 4; j++) {
                uint32_t b0, b1, b2, b3;
                LDSM4(b0, b1, b2, b3, Badr + 4 * SWZ(br_ + j * 16, c2b + bc4));
                uint32_t blo[2] = { b0, b1 }, bhi[2] = { b2, b3 };
                mma16816(acc[0][2 * j],     a[0], blo);
                mma16816(acc[0][2 * j + 1], a[0], bhi);
                mma16816(acc[1][2 * j],     a[1], blo);
                mma16816(acc[1][2 * j + 1], a[1], bhi);
            }
        }

        cst++; if (cst == NSTG) { cst = 0; cph ^= 1; }
    }

    const int row0 = blockIdx.y * 128;
    const int col0 = blockIdx.x * 128;

    if (mode == 0) {
#pragma unroll
        for (int mi = 0; mi < 2; mi++) {
            int row = row0 + wm * 32 + mi * 16 + mlane;
#pragma unroll
            for (int ni = 0; ni < 8; ni++) {
                int col = col0 + wn * 64 + ni * 8 + 2 * klane;
                *(float2*)&C[(size_t)row * N + col] =
                    make_float2(acc[mi][ni][0], acc[mi][ni][1]);
                *(float2*)&C[(size_t)(row + 8) * N + col] =
                    make_float2(acc[mi][ni][2], acc[mi][ni][3]);
            }
        }
        return;
    }

    // QKV epilogue. Region uniform per CTA (col0 multiple of 128).
#pragma unroll
    for (int mi = 0; mi < 2; mi++) {
        int s0 = row0 + wm * 32 + mi * 16 + mlane;
#pragma unroll
        for (int ni = 0; ni < 8; ni++) {
            int c = col0 + wn * 64 + ni * 8 + 2 * klane;
            if (c < 4096) {
                // Q: rope, fp32 out [s][h][128]
                int h = c >> 7, i2 = (c & 127) >> 1;
#pragma unroll
                for (int g = 0; g < 2; g++) {
                    int s = s0 + g * 8;
                    float cs = fc[s * 64 + i2], sn = fs[s * 64 + i2];
                    float av = acc[mi][ni][2 * g], bv = acc[mi][ni][2 * g + 1];
                    *(float2*)&Qo[((size_t)s * N_HEADS + h) * HD + 2 * i2] =
                        make_float2(av * cs - bv * sn, av * sn + bv * cs);
                }
            } else if (c < 5120) {
                // K: rope + hi/lo split into attention tiles
                int kc = c - 4096;
                int kv = kc >> 7, i2 = (kc & 127) >> 1;
#pragma unroll
                for (int g = 0; g < 2; g++) {
                    int s = s0 + g * 8;
                    float cs = fc[s * 64 + i2], sn = fs[s * 64 + i2];
                    float av = acc[mi][ni][2 * g], bv = acc[mi][ni][2 * g + 1];
                    uint32_t hi, lo;
                    split2(av * cs - bv * sn, av * sn + bv * cs, hi, lo);
                    int t = kv * 32 + (s >> 6), r = s & 63;
                    size_t off = (size_t)t * 8192 + KSWZ(r, i2);
                    Khl[off] = hi;
                    Khl[off + 4096] = lo;
                }
            } else {
                // V: fp32 out [s][kv][128]
                int vc = c - 5120;
                int kv = vc >> 7, d = vc & 127;
#pragma unroll
                for (int g = 0; g < 2; g++) {
                    int s = s0 + g * 8;
                    *(float2*)&Vo[((size_t)s * N_KV + kv) * HD + d] =
                        make_float2(acc[mi][ni][2 * g], acc[mi][ni][2 * g + 1]);
                }
            }
        }
    }
}

// ---------------------------------------------------------------------------
// Transpose + fp16 + pack weights (colblk0 = destination column-block offset)
// ---------------------------------------------------------------------------
__global__ void transpose_pack_kernel(const float* __restrict__ W, uint32_t* __restrict__ P,
                                      int R, int C, int colblk0) {
    __shared__ float t[32][33];
    int bx = blockIdx.x * 32;
    int by = blockIdx.y * 32;
    int tx = threadIdx.x, ty = threadIdx.y;
#pragma unroll
    for (int i = 0; i < 32; i += 8)
        t[ty + i][tx] = W[(size_t)(by + ty + i) * C + bx + tx];
    __syncthreads();
    const int nch = R >> 6;
    const int kk2 = tx & 15;
    const int kglob = by + 2 * kk2;
    const int chunk = kglob >> 6;
    const int c2 = (kglob & 63) >> 1;
    const int nbase = (tx >> 4) * 8 + ty;
#pragma unroll
    for (int g = 0; g < 2; g++) {
        int nloc = nbase + g * 16;
        int n = bx + nloc;
        int colblk = colblk0 + (n >> 7), r = n & 127;
        __half2 v = __floats2half2_rn(t[2 * kk2][nloc], t[2 * kk2 + 1][nloc]);
        P[((size_t)colblk * nch + chunk) * TILE_U32 + SWZ(r, c2)] = *(uint32_t*)&v;
    }
}

// ---------------------------------------------------------------------------
// fp16 + pack activations
// ---------------------------------------------------------------------------
__global__ void pack_x_kernel(const float* __restrict__ X, uint32_t* __restrict__ P, int K) {
    int idx = blockIdx.x * blockDim.x + threadIdx.x;
    int perrow = K >> 2;
    int s = idx / perrow;
    int d4 = (idx % perrow) << 2;
    float4 v = *(const float4*)&X[(size_t)s * K + d4];
    int rowblk = s >> 7, r = s & 127;
    int chunk = d4 >> 6;
    int c2 = (d4 & 63) >> 1;
    int nch = K >> 6;
    __half2 lo = __floats2half2_rn(v.x, v.y);
    __half2 hi = __floats2half2_rn(v.z, v.w);
    uint32_t* dst = &P[((size_t)rowblk * nch + chunk) * TILE_U32 + SWZ(r, c2)];
    *(uint2*)dst = make_uint2(*(uint32_t*)&lo, *(uint32_t*)&hi);
}

// ---------------------------------------------------------------------------
// Pack V^T fp16 tiles: [kv][s-chunk][d=128][s half2 swizzled]
// ---------------------------------------------------------------------------
__global__ void pack_vt(const float* __restrict__ V, uint32_t* __restrict__ P) {
    __shared__ float t[64][33];
    int c = blockIdx.x;
    int kv = blockIdx.y;
    int dg = blockIdx.z;
    int tx = threadIdx.x, ty = threadIdx.y;
    int s0 = c * 64, d0 = dg * 32;
#pragma unroll
    for (int ss = ty; ss < 64; ss += 8)
        t[ss][tx] = V[((size_t)(s0 + ss) * N_KV + kv) * HD + d0 + tx];
    __syncthreads();
    int tile = kv * 32 + c;
    int r = d0 + tx;
#pragma unroll
    for (int jj = ty; jj < 32; jj += 8) {
        __half2 v = __floats2half2_rn(t[2 * jj][tx], t[2 * jj + 1][tx]);
        P[(size_t)tile * 4096 + VSWZ(r, jj)] = *(uint32_t*)&v;
    }
}

// ---------------------------------------------------------------------------
// Tensor-core flash attention (causal), ldmatrix-fed.
// ---------------------------------------------------------------------------
#define FA_STAGE 49152
#define FA_SMEM (1024 + 2 * FA_STAGE)

__global__ __launch_bounds__(128, 2)
void fa_kernel(const float* __restrict__ Q, const uint32_t* __restrict__ Kp,
               const uint32_t* __restrict__ Vp, uint32_t* __restrict__ O) {
    extern __shared__ char smem[];
    const uint32_t sb = smem_u32(smem);
    const int tid = threadIdx.x;
    const int w = tid >> 5, lane = tid & 31;
    const int lq = lane >> 3, lr = lane & 7;
    const int h = blockIdx.y;
    const int kvh = h >> 2;
    const int qblk = blockIdx.x;
    const int q0 = qblk * 64;

    if (tid == 0) { MBARRIER_INIT(sb + 0, 1); MBARRIER_INIT(sb + 8, 1); }
    __syncthreads();

    const float scale = 0.08838834764831845f;
    const int rq = q0 + w * 16 + (lane >> 2);
    const float* Qr0 = Q + ((size_t)rq * N_HEADS + h) * HD;
    const float* Qr1 = Q + ((size_t)(rq + 8) * N_HEADS + h) * HD;
    uint32_t qh[8][4], ql[8][4];
#pragma unroll
    for (int kk = 0; kk < 8; kk++) {
        int d0 = kk * 16 + 2 * (lane & 3);
        float2 v00 = *(const float2*)(Qr0 + d0);
        float2 v10 = *(const float2*)(Qr1 + d0);
        float2 v01 = *(const float2*)(Qr0 + d0 + 8);
        float2 v11 = *(const float2*)(Qr1 + d0 + 8);
        split2(v00.x * scale, v00.y * scale, qh[kk][0], ql[kk][0]);
        split2(v10.x * scale, v10.y * scale, qh[kk][1], ql[kk][1]);
        split2(v01.x * scale, v01.y * scale, qh[kk][2], ql[kk][2]);
        split2(v11.x * scale, v11.y * scale, qh[kk][3], ql[kk][3]);
    }

    const int nc = qblk + 1;
    const uint32_t* Kt = Kp + (size_t)(kvh * 32) * 8192;
    const uint32_t* Vt = Vp + (size_t)(kvh * 32) * 4096;

    auto issue = [&](int c) {
        int st = c & 1;
        uint32_t base = sb + 1024 + st * FA_STAGE;
        MBARRIER_EXPECT_TX(sb + 8 * st, FA_STAGE);
        bulk_g2s(base, Kt + (size_t)c * 8192, 32768, sb + 8 * st);
        bulk_g2s(base + 32768, Vt + (size_t)c * 4096, 16384, sb + 8 * st);
    };
    if (tid == 0) { issue(0); if (nc > 1) issue(1); }

    float m0 = -1e30f, m1 = -1e30f, l0 = 0.f, l1 = 0.f;
    float oacc[16][4];
#pragma unroll
    for (int i = 0; i < 16; i++)
#pragma unroll
        for (int j = 0; j < 4; j++) oacc[i][j] = 0.f;

    int ph0 = 0, ph1 = 0;
    // ldmatrix lane rows for S phase (K tile) and PV (Vt tile)
    const int sbrow = (lq >> 1) * 8 + lr;   // + 16j
    const int sbc4 = (lq & 1) * 4;

    for (int c = 0; c < nc; c++) {
        const int st = c & 1;
        if (st == 0) { MBARRIER_WAIT_PARITY(sb + 0, ph0); ph0 ^= 1; }
        else         { MBARRIER_WAIT_PARITY(sb + 8, ph1); ph1 ^= 1; }

        const uint32_t KhA = sb + 1024 + st * FA_STAGE;
        const uint32_t KlA = KhA + 16384;
        const uint32_t VsA = KhA + 32768;

        // S = Q K^T (hi/lo 3-pass)
        float sacc[8][4];
#pragma unroll
        for (int nt = 0; nt < 8; nt++)
#pragma unroll
            for (int j = 0; j < 4; j++) sacc[nt][j] = 0.f;

#pragma unroll
        for (int kk = 0; kk < 8; kk++) {
            const int c2b = kk * 8 + sbc4;
#pragma unroll
            for (int j = 0; j < 4; j++) {
                uint32_t adr = 4 * KSWZ(sbrow + j * 16, c2b);
                uint32_t h0, h1, h2, h3, l0r, l1r, l2r, l3r;
                LDSM4(h0, h1, h2, h3, KhA + adr);
                LDSM4(l0r, l1r, l2r, l3r, KlA + adr);
                uint32_t bh0[2] = { h0, h1 }, bh1[2] = { h2, h3 };
                uint32_t bl0[2] = { l0r, l1r }, bl1[2] = { l2r, l3r };
                mma16816(sacc[2 * j],     qh[kk], bh0);
                mma16816(sacc[2 * j],     ql[kk], bh0);
                mma16816(sacc[2 * j],     qh[kk], bl0);
                mma16816(sacc[2 * j + 1], qh[kk], bh1);
                mma16816(sacc[2 * j + 1], ql[kk], bh1);
                mma16816(sacc[2 * j + 1], qh[kk], bl1);
            }
        }

        // causal mask on diagonal chunk
        if (c == qblk) {
#pragma unroll
            for (int nt = 0; nt < 8; nt++) {
                int cg = c * 64 + nt * 8 + 2 * (lane & 3);
                if (cg > rq)          sacc[nt][0] = -1e30f;
                if (cg + 1 > rq)      sacc[nt][1] = -1e30f;
                if (cg > rq + 8)      sacc[nt][2] = -1e30f;
                if (cg + 1 > rq + 8)  sacc[nt][3] = -1e30f;
            }
        }

        // online softmax
        float mx0 = -1e30f, mx1 = -1e30f;
#pragma unroll
        for (int nt = 0; nt < 8; nt++) {
            mx0 = fmaxf(mx0, fmaxf(sacc[nt][0], sacc[nt][1]));
            mx1 = fmaxf(mx1, fmaxf(sacc[nt][2], sacc[nt][3]));
        }
        mx0 = fmaxf(mx0, __shfl_xor_sync(0xffffffff, mx0, 1));
        mx0 = fmaxf(mx0, __shfl_xor_sync(0xffffffff, mx0, 2));
        mx1 = fmaxf(mx1, __shfl_xor_sync(0xffffffff, mx1, 1));
        mx1 = fmaxf(mx1, __shfl_xor_sync(0xffffffff, mx1, 2));
        float mn0 = fmaxf(m0, mx0), mn1 = fmaxf(m1, mx1);
        float cor0 = __expf(m0 - mn0), cor1 = __expf(m1 - mn1);
        l0 *= cor0; l1 *= cor1;
#pragma unroll
        for (int i = 0; i < 16; i++) {
            oacc[i][0] *= cor0; oacc[i][1] *= cor0;
            oacc[i][2] *= cor1; oacc[i][3] *= cor1;
        }
        float rs0 = 0.f, rs1 = 0.f;
        uint32_t pf[4][4];
#pragma unroll
        for (int nt = 0; nt < 8; nt++) {
            float p0 = __expf(sacc[nt][0] - mn0);
            float p1 = __expf(sacc[nt][1] - mn0);
            float p2 = __expf(sacc[nt][2] - mn1);
            float p3 = __expf(sacc[nt][3] - mn1);
            rs0 += p0 + p1; rs1 += p2 + p3;
            __half2 h01 = __floats2half2_rn(p0, p1);
            __half2 h23 = __floats2half2_rn(p2, p3);
            int kt = nt >> 1, hi = (nt & 1) << 1;
            pf[kt][hi]     = *(uint32_t*)&h01;
            pf[kt][hi + 1] = *(uint32_t*)&h23;
        }
        rs0 += __shfl_xor_sync(0xffffffff, rs0, 1);
        rs0 += __shfl_xor_sync(0xffffffff, rs0, 2);
        rs1 += __shfl_xor_sync(0xffffffff, rs1, 1);
        rs1 += __shfl_xor_sync(0xffffffff, rs1, 2);
        l0 += rs0; l1 += rs1;
        m0 = mn0; m1 = mn1;

        // O += P V   (jj = d-rowpair of Vt)
#pragma unroll
        for (int jj = 0; jj < 8; jj++) {
#pragma unroll
            for (int kt = 0; kt < 4; kt++) {
                uint32_t b0, b1, b2, b3;
                LDSM4(b0, b1, b2, b3,
                      VsA + 4 * VSWZ(sbrow + jj * 16, kt * 8 + sbc4));
                uint32_t blo[2] = { b0, b1 }, bhi[2] = { b2, b3 };
                mma16816(oacc[2 * jj],     pf[kt], blo);
                mma16816(oacc[2 * jj + 1], pf[kt], bhi);
            }
        }

        __syncthreads();
        if (tid == 0 && c + 2 < nc) issue(c + 2);
    }

    // Epilogue: fp16 packed-tile output for W_o GEMM
    float i0 = 1.f / l0, i1 = 1.f / l1;
    const int s0r = rq, s1r = rq + 8;
    const int rb0 = s0r >> 7, ri0 = s0r & 127;
    const int rb1 = s1r >> 7, ri1 = s1r & 127;
#pragma unroll
    for (int nt2 = 0; nt2 < 16; nt2++) {
        int d = nt2 * 8 + 2 * (lane & 3);
        int gdim = h * HD + d;
        int chunk = gdim >> 6;
        int c2 = (gdim & 63) >> 1;
        __half2 vlo = __floats2half2_rn(oacc[nt2][0] * i0, oacc[nt2][1] * i0);
        __half2 vhi = __floats2half2_rn(oacc[nt2][2] * i1, oacc[nt2][3] * i1);
        O[((size_t)rb0 * 64 + chunk) * TILE_U32 + SWZ(ri0, c2)] = *(uint32_t*)&vlo;
        O[((size_t)rb1 * 64 + chunk) * TILE_U32 + SWZ(ri1, c2)] = *(uint32_t*)&vhi;
    }
}

// ---------------------------------------------------------------------------
// Host launcher
// ---------------------------------------------------------------------------
extern "C" void kernel_launch(void* const* d_in, const int* in_sizes, int n_in,
                              void* d_out, int out_size) {
    const float* x  = (const float*)d_in[0];
    const float* fc = (const float*)d_in[1];
    const float* fs = (const float*)d_in[2];
    const float* wq = (const float*)d_in[4];
    const float* wk = (const float*)d_in[5];
    const float* wv = (const float*)d_in[6];
    const float* wo = (const float*)d_in[7];
    float* out = (float*)d_out;

    float *qp, *vp;
    uint32_t *ap, *xp, *wqkv, *woT, *khl, *vt;
    cudaGetSymbolAddress((void**)&qp, g_q);
    cudaGetSymbolAddress((void**)&vp, g_v);
    cudaGetSymbolAddress((void**)&ap, g_attn);
    cudaGetSymbolAddress((void**)&xp, g_xp);
    cudaGetSymbolAddress((void**)&wqkv, g_wqkv);
    cudaGetSymbolAddress((void**)&woT, g_woT);
    cudaGetSymbolAddress((void**)&khl, g_khl);
    cudaGetSymbolAddress((void**)&vt, g_vt);

    cudaFuncSetAttribute(mma_gemm, cudaFuncAttributeMaxDynamicSharedMemorySize, GEMM_SMEM);
    cudaFuncSetAttribute(fa_kernel, cudaFuncAttributeMaxDynamicSharedMemorySize, FA_SMEM);

    // Pack weights into fused B ([wq|wk|wv] -> colblks 0-31,32-39,40-47) + wo
    transpose_pack_kernel<<<dim3(4096 / 32, 4096 / 32), dim3(32, 8)>>>(wq, wqkv, 4096, 4096, 0);
    {
        int n4 = S_LEN * D_MODEL / 4;
        pack_x_kernel<<<(n4 + 255) / 256, 256>>>(x, xp, D_MODEL);
    }
    transpose_pack_kernel<<<dim3(1024 / 32, 4096 / 32), dim3(32, 8)>>>(wk, wqkv, 4096, 1024, 32);
    transpose_pack_kernel<<<dim3(1024 / 32, 4096 / 32), dim3(32, 8)>>>(wv, wqkv, 4096, 1024, 40);
    transpose_pack_kernel<<<dim3(4096 / 32, 4096 / 32), dim3(32, 8)>>>(wo, woT, 4096, 4096, 0);

    // Fused QKV projection + rope + packing epilogues
    mma_gemm<<<dim3(48, S_LEN / 128), 256, GEMM_SMEM>>>(
        xp, wqkv, nullptr, S_LEN, 6144, 4096, 1, fc, fs, qp, khl, vp);

    // V^T tiles
    pack_vt<<<dim3(32, 8, 4), dim3(32, 8)>>>(vp, vt);

    // Flash attention (tensor cores)
    fa_kernel<<<dim3(S_LEN / 64, N_HEADS), 128, FA_SMEM>>>(qp, khl, vt, ap);

    // Output projection
    mma_gemm<<<dim3(4096 / 128, S_LEN / 128), 256, GEMM_SMEM>>>(
        ap, woT, out, S_LEN, 4096, 4096, 0, nullptr, nullptr, nullptr, nullptr, nullptr);
}

// round 9
// speedup vs baseline: 20.7305x; 1.0261x over previous
#include <cuda_runtime.h>
#include <cuda_fp16.h>
#include <cstdint>

// Shapes (fixed)
#define S_LEN 2048
#define D_MODEL 4096
#define N_HEADS 32
#define N_KV 8
#define HD 128

// Scratch (allocation-free rule: device globals)
__device__ float    g_q[S_LEN * N_HEADS * HD];          // fp32 Q (rope'd)
__device__ uint32_t g_attn[S_LEN * N_HEADS * HD / 2];   // fp16 packed tiles
__device__ uint32_t g_xp[S_LEN * D_MODEL / 2];          // fp16 packed x
__device__ uint32_t g_wqkv[48 * 64 * 4096];             // packed [wq|wk|wv]
__device__ uint32_t g_woT[4096 * 4096 / 2];
__device__ uint32_t g_khl[8 * 32 * 8192];               // K hi+lo fp16 tiles
__device__ uint32_t g_vt[8 * 32 * 4096];                // V^T fp16 tiles

// GEMM packed tile: [rowblk(128)][chunk(64 k)][128 x 32 half2], swizzled
#define SWZ(r, c2) (((r) << 5) + ((c2) ^ (((r) & 7) << 2)))
#define TILE_U32 4096
#define TILE_B 16384
// Attention K tile: [64 r][64 half2]; V^T tile: [128 d][32 half2]
#define KSWZ(r, c2) (((r) << 6) + ((c2) ^ (((r) & 7) << 2)))
#define VSWZ(r, c2) (((r) << 5) + ((c2) ^ (((r) & 7) << 2)))

// ---------------------------------------------------------------------------
// Helpers (baseline PTX only)
// ---------------------------------------------------------------------------
__device__ __forceinline__ uint32_t smem_u32(const void* p) {
    uint32_t a;
    asm("{ .reg .u64 t; cvta.to.shared.u64 t, %1; cvt.u32.u64 %0, t; }" : "=r"(a) : "l"(p));
    return a;
}
#define MBARRIER_INIT(mbar, cnt) \
    asm volatile("mbarrier.init.shared.b64 [%0], %1;" :: "r"((uint32_t)(mbar)), "r"((uint32_t)(cnt)) : "memory")
#define MBARRIER_EXPECT_TX(mbar, bytes) \
    asm volatile("mbarrier.arrive.expect_tx.shared.b64 _, [%0], %1;" :: "r"((uint32_t)(mbar)), "r"((uint32_t)(bytes)) : "memory")
#define MBARRIER_WAIT_PARITY(mbar, par) do {                                        \
    uint32_t _m = (uint32_t)(mbar); uint32_t _p = (uint32_t)(par); uint32_t _d;     \
    asm volatile("{\n\t.reg .pred p;\n\t"                                           \
        "mbarrier.try_wait.parity.acquire.cta.shared::cta.b64 p, [%1], %2;\n\t"     \
        "selp.b32 %0, 1, 0, p;\n\t}" : "=r"(_d) : "r"(_m), "r"(_p) : "memory");     \
    if (!_d) {                                                                      \
        asm volatile("{\n\t.reg .pred P1;\n\t"                                      \
            "WL_%=:\n\t"                                                            \
            "mbarrier.try_wait.parity.acquire.cta.shared::cta.b64 P1, [%0], %1, 0x989680;\n\t" \
            "@P1 bra.uni WD_%=;\n\t"                                                \
            "bra.uni WL_%=;\n\t"                                                    \
            "WD_%=:\n\t}" :: "r"(_m), "r"(_p) : "memory");                          \
    }                                                                               \
} while (0)

__device__ __forceinline__ void bulk_g2s(uint32_t dst, const void* src,
                                         uint32_t bytes, uint32_t mbar) {
    asm volatile(
        "cp.async.bulk.shared::cluster.global.mbarrier::complete_tx::bytes [%0], [%1], %2, [%3];"
        :: "r"(dst), "l"(src), "r"(bytes), "r"(mbar) : "memory");
}

__device__ __forceinline__ void mma16816(float* d, const uint32_t* a, const uint32_t* b) {
    asm volatile(
        "mma.sync.aligned.m16n8k16.row.col.f32.f16.f16.f32 "
        "{%0,%1,%2,%3}, {%4,%5,%6,%7}, {%8,%9}, {%0,%1,%2,%3};"
        : "+f"(d[0]), "+f"(d[1]), "+f"(d[2]), "+f"(d[3])
        : "r"(a[0]), "r"(a[1]), "r"(a[2]), "r"(a[3]), "r"(b[0]), "r"(b[1]));
}

#define LDSM4(r0, r1, r2, r3, addr) \
    asm volatile("ldmatrix.sync.aligned.m8n8.x4.shared.b16 {%0,%1,%2,%3}, [%4];" \
                 : "=r"(r0), "=r"(r1), "=r"(r2), "=r"(r3) : "r"(addr))

__device__ __forceinline__ void split2(float x, float y,
                                       uint32_t& hi, uint32_t& lo) {
    __half hx = __float2half_rn(x), hy = __float2half_rn(y);
    __half lx = __float2half_rn(x - __half2float(hx));
    __half ly = __float2half_rn(y - __half2float(hy));
    __half2 H = __halves2half2(hx, hy), L = __halves2half2(lx, ly);
    hi = *(uint32_t*)&H; lo = *(uint32_t*)&L;
}

// ---------------------------------------------------------------------------
// fp16 mma.sync GEMM, ldmatrix-fed. mode 0: plain fp32 C store.
// mode 1: QKV epilogue (Q rope fp32 / K rope+split pack / V -> V^T tiles).
// ---------------------------------------------------------------------------
#define STAGE_B (2 * TILE_B)
#define NSTG 3
#define GEMM_SMEM (1024 + NSTG * STAGE_B)

__global__ __launch_bounds__(256, 2)
void mma_gemm(const uint32_t* __restrict__ Ap, const uint32_t* __restrict__ Bp,
              float* __restrict__ C, int M, int N, int K, int mode,
              const float* __restrict__ fc, const float* __restrict__ fs,
              float* __restrict__ Qo, uint32_t* __restrict__ Khl,
              uint32_t* __restrict__ Vt) {
    extern __shared__ char smem[];
    const uint32_t sb = smem_u32(smem);
    const int tid = threadIdx.x;
    const int wid = tid >> 5, lane = tid & 31;
    const int wm = wid & 3;
    const int wn = wid >> 2;
    const int mlane = lane >> 2;
    const int klane = lane & 3;
    const int lq = lane >> 3, lr = lane & 7;
    const int nch = K >> 6;

    if (tid == 0) {
#pragma unroll
        for (int s = 0; s < NSTG; s++) MBARRIER_INIT(sb + 8 * s, 1);
    }
    __syncthreads();

    const uint32_t* Abase = Ap + (size_t)blockIdx.y * nch * TILE_U32;
    const uint32_t* Bbase = Bp + (size_t)blockIdx.x * nch * TILE_U32;

    auto issue = [&](int chunk, int st) {
        uint32_t base = sb + 1024 + st * STAGE_B;
        MBARRIER_EXPECT_TX(sb + 8 * st, STAGE_B);
        bulk_g2s(base, Abase + (size_t)chunk * TILE_U32, TILE_B, sb + 8 * st);
        bulk_g2s(base + TILE_B, Bbase + (size_t)chunk * TILE_U32, TILE_B, sb + 8 * st);
    };

    if (tid == 0) { issue(0, 0); issue(1, 1); }

    float acc[2][8][4];
#pragma unroll
    for (int mi = 0; mi < 2; mi++)
#pragma unroll
        for (int ni = 0; ni < 8; ni++)
#pragma unroll
            for (int j = 0; j < 4; j++) acc[mi][ni][j] = 0.f;

    const int ar0 = wm * 32 + (lq & 1) * 8 + lr;
    const int ac4 = (lq >> 1) * 4;
    const int br_ = wn * 64 + (lq >> 1) * 8 + lr;
    const int bc4 = (lq & 1) * 4;

    int cst = 0, cph = 0;
    int pk = 2, pst = 2;

    for (int it = 0; it < nch; it++) {
        __syncthreads();
        if (pk < nch) {
            if (tid == 0) issue(pk, pst);
            pk++; pst++; if (pst == NSTG) pst = 0;
        }
        MBARRIER_WAIT_PARITY(sb + 8 * cst, cph);

        const uint32_t Aadr = sb + 1024 + cst * STAGE_B;
        const uint32_t Badr = Aadr + TILE_B;

#pragma unroll
        for (int s = 0; s < 4; s++) {
            const int c2b = s * 8;
            uint32_t a[2][4];
            LDSM4(a[0][0], a[0][1], a[0][2], a[0][3],
                  Aadr + 4 * SWZ(ar0, c2b + ac4));
            LDSM4(a[1][0], a[1][1], a[1][2], a[1][3],
                  Aadr + 4 * SWZ(ar0 + 16, c2b + ac4));
#pragma unroll
            for (int j = 0; j < 4; j++) {
                uint32_t b0, b1, b2, b3;
                LDSM4(b0, b1, b2, b3, Badr + 4 * SWZ(br_ + j * 16, c2b + bc4));
                uint32_t blo[2] = { b0, b1 }, bhi[2] = { b2, b3 };
                mma16816(acc[0][2 * j],     a[0], blo);
                mma16816(acc[0][2 * j + 1], a[0], bhi);
                mma16816(acc[1][2 * j],     a[1], blo);
                mma16816(acc[1][2 * j + 1], a[1], bhi);
            }
        }

        cst++; if (cst == NSTG) { cst = 0; cph ^= 1; }
    }

    const int row0 = blockIdx.y * 128;
    const int col0 = blockIdx.x * 128;

    if (mode == 0) {
#pragma unroll
        for (int mi = 0; mi < 2; mi++) {
            int row = row0 + wm * 32 + mi * 16 + mlane;
#pragma unroll
            for (int ni = 0; ni < 8; ni++) {
                int col = col0 + wn * 64 + ni * 8 + 2 * klane;
                *(float2*)&C[(size_t)row * N + col] =
                    make_float2(acc[mi][ni][0], acc[mi][ni][1]);
                *(float2*)&C[(size_t)(row + 8) * N + col] =
                    make_float2(acc[mi][ni][2], acc[mi][ni][3]);
            }
        }
        return;
    }

    // QKV epilogue. Region uniform per CTA (col0 multiple of 128).
    if (col0 < 4096) {
        // Q: rope, fp32 out [s][h][128]
#pragma unroll
        for (int mi = 0; mi < 2; mi++) {
            int s0 = row0 + wm * 32 + mi * 16 + mlane;
#pragma unroll
            for (int ni = 0; ni < 8; ni++) {
                int c = col0 + wn * 64 + ni * 8 + 2 * klane;
                int h = c >> 7, i2 = (c & 127) >> 1;
#pragma unroll
                for (int g = 0; g < 2; g++) {
                    int s = s0 + g * 8;
                    float cs = fc[s * 64 + i2], sn = fs[s * 64 + i2];
                    float av = acc[mi][ni][2 * g], bv = acc[mi][ni][2 * g + 1];
                    *(float2*)&Qo[((size_t)s * N_HEADS + h) * HD + 2 * i2] =
                        make_float2(av * cs - bv * sn, av * sn + bv * cs);
                }
            }
        }
    } else if (col0 < 5120) {
        // K: rope + hi/lo split into attention tiles
#pragma unroll
        for (int mi = 0; mi < 2; mi++) {
            int s0 = row0 + wm * 32 + mi * 16 + mlane;
#pragma unroll
            for (int ni = 0; ni < 8; ni++) {
                int kc = col0 - 4096 + wn * 64 + ni * 8 + 2 * klane;
                int kv = kc >> 7, i2 = (kc & 127) >> 1;
#pragma unroll
                for (int g = 0; g < 2; g++) {
                    int s = s0 + g * 8;
                    float cs = fc[s * 64 + i2], sn = fs[s * 64 + i2];
                    float av = acc[mi][ni][2 * g], bv = acc[mi][ni][2 * g + 1];
                    uint32_t hi, lo;
                    split2(av * cs - bv * sn, av * sn + bv * cs, hi, lo);
                    int t = kv * 32 + (s >> 6), r = s & 63;
                    size_t off = (size_t)t * 8192 + KSWZ(r, i2);
                    Khl[off] = hi;
                    Khl[off + 4096] = lo;
                }
            }
        }
    } else {
        // V: stage fp16 in smem, then emit V^T tiles directly.
        // This CTA covers kv = colblk-40 (full d 0..127) x s rows row0..row0+127
        // = exactly 2 V^T tiles [128 d][32 s-half2].
        uint32_t* st = (uint32_t*)(smem + 1024);    // [128 s][65 d-half2 pitch]
        __syncthreads();                            // all pipe reads done; reuse smem
#pragma unroll
        for (int mi = 0; mi < 2; mi++) {
            int sl0 = wm * 32 + mi * 16 + mlane;    // local s
#pragma unroll
            for (int ni = 0; ni < 8; ni++) {
                int d = wn * 64 + ni * 8 + 2 * klane;   // within-head dim (even)
#pragma unroll
                for (int g = 0; g < 2; g++) {
                    __half2 v = __floats2half2_rn(acc[mi][ni][2 * g],
                                                  acc[mi][ni][2 * g + 1]);
                    st[(sl0 + g * 8) * 65 + (d >> 1)] = *(uint32_t*)&v;
                }
            }
        }
        __syncthreads();
        const int kv = blockIdx.x - 40;
        const int tile0 = kv * 32 + (row0 >> 6);
        for (int i = tid; i < 8192; i += 256) {
            int d = i & 127;
            int jj = (i >> 7) & 31;
            int ch = i >> 12;               // 0 or 1 (s-chunk)
            int sl = ch * 64 + 2 * jj;
            uint32_t u0 = st[sl * 65 + (d >> 1)];
            uint32_t u1 = st[(sl + 1) * 65 + (d >> 1)];
            __half h0 = (d & 1) ? ((__half2*)&u0)->y : ((__half2*)&u0)->x;
            __half h1 = (d & 1) ? ((__half2*)&u1)->y : ((__half2*)&u1)->x;
            __half2 out = __halves2half2(h0, h1);
            Vt[(size_t)(tile0 + ch) * 4096 + VSWZ(d, jj)] = *(uint32_t*)&out;
        }
    }
}

// ---------------------------------------------------------------------------
// Merged weight pack: z=0 wq, z=1 wk, z=2 wv, z=3 wo. R=4096 all.
// ---------------------------------------------------------------------------
__global__ void pack_w_all(const float* __restrict__ wq, const float* __restrict__ wk,
                           const float* __restrict__ wv, const float* __restrict__ wo,
                           uint32_t* __restrict__ wqkv, uint32_t* __restrict__ woT) {
    const int z = blockIdx.z;
    const float* W; uint32_t* P; int C; int colblk0;
    if (z == 0)      { W = wq; P = wqkv; C = 4096; colblk0 = 0; }
    else if (z == 1) { W = wk; P = wqkv; C = 1024; colblk0 = 32; }
    else if (z == 2) { W = wv; P = wqkv; C = 1024; colblk0 = 40; }
    else             { W = wo; P = woT;  C = 4096; colblk0 = 0; }
    int bx = blockIdx.x * 32;
    if (bx >= C) return;
    int by = blockIdx.y * 32;

    __shared__ float t[32][33];
    int tx = threadIdx.x, ty = threadIdx.y;
#pragma unroll
    for (int i = 0; i < 32; i += 8)
        t[ty + i][tx] = W[(size_t)(by + ty + i) * C + bx + tx];
    __syncthreads();
    const int kk2 = tx & 15;
    const int kglob = by + 2 * kk2;
    const int chunk = kglob >> 6;
    const int c2 = (kglob & 63) >> 1;
    const int nbase = (tx >> 4) * 8 + ty;
#pragma unroll
    for (int g = 0; g < 2; g++) {
        int nloc = nbase + g * 16;
        int n = bx + nloc;
        int colblk = colblk0 + (n >> 7), r = n & 127;
        __half2 v = __floats2half2_rn(t[2 * kk2][nloc], t[2 * kk2 + 1][nloc]);
        P[((size_t)colblk * 64 + chunk) * TILE_U32 + SWZ(r, c2)] = *(uint32_t*)&v;
    }
}

// ---------------------------------------------------------------------------
// fp16 + pack activations
// ---------------------------------------------------------------------------
__global__ void pack_x_kernel(const float* __restrict__ X, uint32_t* __restrict__ P, int K) {
    int idx = blockIdx.x * blockDim.x + threadIdx.x;
    int perrow = K >> 2;
    int s = idx / perrow;
    int d4 = (idx % perrow) << 2;
    float4 v = *(const float4*)&X[(size_t)s * K + d4];
    int rowblk = s >> 7, r = s & 127;
    int chunk = d4 >> 6;
    int c2 = (d4 & 63) >> 1;
    int nch = K >> 6;
    __half2 lo = __floats2half2_rn(v.x, v.y);
    __half2 hi = __floats2half2_rn(v.z, v.w);
    uint32_t* dst = &P[((size_t)rowblk * nch + chunk) * TILE_U32 + SWZ(r, c2)];
    *(uint2*)dst = make_uint2(*(uint32_t*)&lo, *(uint32_t*)&hi);
}

// ---------------------------------------------------------------------------
// Tensor-core flash attention (causal), ldmatrix-fed, LPT-ordered.
// ---------------------------------------------------------------------------
#define FA_STAGE 49152
#define FA_SMEM (1024 + 2 * FA_STAGE)

__global__ __launch_bounds__(128, 2)
void fa_kernel(const float* __restrict__ Q, const uint32_t* __restrict__ Kp,
               const uint32_t* __restrict__ Vp, uint32_t* __restrict__ O) {
    extern __shared__ char smem[];
    const uint32_t sb = smem_u32(smem);
    const int tid = threadIdx.x;
    const int w = tid >> 5, lane = tid & 31;
    const int lq = lane >> 3, lr = lane & 7;
    const int h = blockIdx.y;
    const int kvh = h >> 2;
    const int qblk = gridDim.x - 1 - blockIdx.x;    // LPT: longest CTAs first
    const int q0 = qblk * 64;

    if (tid == 0) { MBARRIER_INIT(sb + 0, 1); MBARRIER_INIT(sb + 8, 1); }
    __syncthreads();

    const float scale = 0.08838834764831845f;
    const int rq = q0 + w * 16 + (lane >> 2);
    const float* Qr0 = Q + ((size_t)rq * N_HEADS + h) * HD;
    const float* Qr1 = Q + ((size_t)(rq + 8) * N_HEADS + h) * HD;
    uint32_t qh[8][4], ql[8][4];
#pragma unroll
    for (int kk = 0; kk < 8; kk++) {
        int d0 = kk * 16 + 2 * (lane & 3);
        float2 v00 = *(const float2*)(Qr0 + d0);
        float2 v10 = *(const float2*)(Qr1 + d0);
        float2 v01 = *(const float2*)(Qr0 + d0 + 8);
        float2 v11 = *(const float2*)(Qr1 + d0 + 8);
        split2(v00.x * scale, v00.y * scale, qh[kk][0], ql[kk][0]);
        split2(v10.x * scale, v10.y * scale, qh[kk][1], ql[kk][1]);
        split2(v01.x * scale, v01.y * scale, qh[kk][2], ql[kk][2]);
        split2(v11.x * scale, v11.y * scale, qh[kk][3], ql[kk][3]);
    }

    const int nc = qblk + 1;
    const uint32_t* Kt = Kp + (size_t)(kvh * 32) * 8192;
    const uint32_t* Vt = Vp + (size_t)(kvh * 32) * 4096;

    auto issue = [&](int c) {
        int st = c & 1;
        uint32_t base = sb + 1024 + st * FA_STAGE;
        MBARRIER_EXPECT_TX(sb + 8 * st, FA_STAGE);
        bulk_g2s(base, Kt + (size_t)c * 8192, 32768, sb + 8 * st);
        bulk_g2s(base + 32768, Vt + (size_t)c * 4096, 16384, sb + 8 * st);
    };
    if (tid == 0) { issue(0); if (nc > 1) issue(1); }

    float m0 = -1e30f, m1 = -1e30f, l0 = 0.f, l1 = 0.f;
    float oacc[16][4];
#pragma unroll
    for (int i = 0; i < 16; i++)
#pragma unroll
        for (int j = 0; j < 4; j++) oacc[i][j] = 0.f;

    int ph0 = 0, ph1 = 0;
    const int sbrow = (lq >> 1) * 8 + lr;
    const int sbc4 = (lq & 1) * 4;

    for (int c = 0; c < nc; c++) {
        const int st = c & 1;
        if (st == 0) { MBARRIER_WAIT_PARITY(sb + 0, ph0); ph0 ^= 1; }
        else         { MBARRIER_WAIT_PARITY(sb + 8, ph1); ph1 ^= 1; }

        const uint32_t KhA = sb + 1024 + st * FA_STAGE;
        const uint32_t KlA = KhA + 16384;
        const uint32_t VsA = KhA + 32768;

        float sacc[8][4];
#pragma unroll
        for (int nt = 0; nt < 8; nt++)
#pragma unroll
            for (int j = 0; j < 4; j++) sacc[nt][j] = 0.f;

#pragma unroll
        for (int kk = 0; kk < 8; kk++) {
            const int c2b = kk * 8 + sbc4;
#pragma unroll
            for (int j = 0; j < 4; j++) {
                uint32_t adr = 4 * KSWZ(sbrow + j * 16, c2b);
                uint32_t h0, h1, h2, h3, l0r, l1r, l2r, l3r;
                LDSM4(h0, h1, h2, h3, KhA + adr);
                LDSM4(l0r, l1r, l2r, l3r, KlA + adr);
                uint32_t bh0[2] = { h0, h1 }, bh1[2] = { h2, h3 };
                uint32_t bl0[2] = { l0r, l1r }, bl1[2] = { l2r, l3r };
                mma16816(sacc[2 * j],     qh[kk], bh0);
                mma16816(sacc[2 * j],     ql[kk], bh0);
                mma16816(sacc[2 * j],     qh[kk], bl0);
                mma16816(sacc[2 * j + 1], qh[kk], bh1);
                mma16816(sacc[2 * j + 1], ql[kk], bh1);
                mma16816(sacc[2 * j + 1], qh[kk], bl1);
            }
        }

        if (c == qblk) {
#pragma unroll
            for (int nt = 0; nt < 8; nt++) {
                int cg = c * 64 + nt * 8 + 2 * (lane & 3);
                if (cg > rq)          sacc[nt][0] = -1e30f;
                if (cg + 1 > rq)      sacc[nt][1] = -1e30f;
                if (cg > rq + 8)      sacc[nt][2] = -1e30f;
                if (cg + 1 > rq + 8)  sacc[nt][3] = -1e30f;
            }
        }

        float mx0 = -1e30f, mx1 = -1e30f;
#pragma unroll
        for (int nt = 0; nt < 8; nt++) {
            mx0 = fmaxf(mx0, fmaxf(sacc[nt][0], sacc[nt][1]));
            mx1 = fmaxf(mx1, fmaxf(sacc[nt][2], sacc[nt][3]));
        }
        mx0 = fmaxf(mx0, __shfl_xor_sync(0xffffffff, mx0, 1));
        mx0 = fmaxf(mx0, __shfl_xor_sync(0xffffffff, mx0, 2));
        mx1 = fmaxf(mx1, __shfl_xor_sync(0xffffffff, mx1, 1));
        mx1 = fmaxf(mx1, __shfl_xor_sync(0xffffffff, mx1, 2));
        float mn0 = fmaxf(m0, mx0), mn1 = fmaxf(m1, mx1);
        float cor0 = __expf(m0 - mn0), cor1 = __expf(m1 - mn1);
        l0 *= cor0; l1 *= cor1;
#pragma unroll
        for (int i = 0; i < 16; i++) {
            oacc[i][0] *= cor0; oacc[i][1] *= cor0;
            oacc[i][2] *= cor1; oacc[i][3] *= cor1;
        }
        float rs0 = 0.f, rs1 = 0.f;
        uint32_t pf[4][4];
#pragma unroll
        for (int nt = 0; nt < 8; nt++) {
            float p0 = __expf(sacc[nt][0] - mn0);
            float p1 = __expf(sacc[nt][1] - mn0);
            float p2 = __expf(sacc[nt][2] - mn1);
            float p3 = __expf(sacc[nt][3] - mn1);
            rs0 += p0 + p1; rs1 += p2 + p3;
            __half2 h01 = __floats2half2_rn(p0, p1);
            __half2 h23 = __floats2half2_rn(p2, p3);
            int kt = nt >> 1, hi = (nt & 1) << 1;
            pf[kt][hi]     = *(uint32_t*)&h01;
            pf[kt][hi + 1] = *(uint32_t*)&h23;
        }
        rs0 += __shfl_xor_sync(0xffffffff, rs0, 1);
        rs0 += __shfl_xor_sync(0xffffffff, rs0, 2);
        rs1 += __shfl_xor_sync(0xffffffff, rs1, 1);
        rs1 += __shfl_xor_sync(0xffffffff, rs1, 2);
        l0 += rs0; l1 += rs1;
        m0 = mn0; m1 = mn1;

#pragma unroll
        for (int jj = 0; jj < 8; jj++) {
#pragma unroll
            for (int kt = 0; kt < 4; kt++) {
                uint32_t b0, b1, b2, b3;
                LDSM4(b0, b1, b2, b3,
                      VsA + 4 * VSWZ(sbrow + jj * 16, kt * 8 + sbc4));
                uint32_t blo[2] = { b0, b1 }, bhi[2] = { b2, b3 };
                mma16816(oacc[2 * jj],     pf[kt], blo);
                mma16816(oacc[2 * jj + 1], pf[kt], bhi);
            }
        }

        __syncthreads();
        if (tid == 0 && c + 2 < nc) issue(c + 2);
    }

    float i0 = 1.f / l0, i1 = 1.f / l1;
    const int s0r = rq, s1r = rq + 8;
    const int rb0 = s0r >> 7, ri0 = s0r & 127;
    const int rb1 = s1r >> 7, ri1 = s1r & 127;
#pragma unroll
    for (int nt2 = 0; nt2 < 16; nt2++) {
        int d = nt2 * 8 + 2 * (lane & 3);
        int gdim = h * HD + d;
        int chunk = gdim >> 6;
        int c2 = (gdim & 63) >> 1;
        __half2 vlo = __floats2half2_rn(oacc[nt2][0] * i0, oacc[nt2][1] * i0);
        __half2 vhi = __floats2half2_rn(oacc[nt2][2] * i1, oacc[nt2][3] * i1);
        O[((size_t)rb0 * 64 + chunk) * TILE_U32 + SWZ(ri0, c2)] = *(uint32_t*)&vlo;
        O[((size_t)rb1 * 64 + chunk) * TILE_U32 + SWZ(ri1, c2)] = *(uint32_t*)&vhi;
    }
}

// ---------------------------------------------------------------------------
// Host launcher
// ---------------------------------------------------------------------------
extern "C" void kernel_launch(void* const* d_in, const int* in_sizes, int n_in,
                              void* d_out, int out_size) {
    const float* x  = (const float*)d_in[0];
    const float* fc = (const float*)d_in[1];
    const float* fs = (const float*)d_in[2];
    const float* wq = (const float*)d_in[4];
    const float* wk = (const float*)d_in[5];
    const float* wv = (const float*)d_in[6];
    const float* wo = (const float*)d_in[7];
    float* out = (float*)d_out;

    float *qp;
    uint32_t *ap, *xp, *wqkv, *woT, *khl, *vt;
    cudaGetSymbolAddress((void**)&qp, g_q);
    cudaGetSymbolAddress((void**)&ap, g_attn);
    cudaGetSymbolAddress((void**)&xp, g_xp);
    cudaGetSymbolAddress((void**)&wqkv, g_wqkv);
    cudaGetSymbolAddress((void**)&woT, g_woT);
    cudaGetSymbolAddress((void**)&khl, g_khl);
    cudaGetSymbolAddress((void**)&vt, g_vt);

    cudaFuncSetAttribute(mma_gemm, cudaFuncAttributeMaxDynamicSharedMemorySize, GEMM_SMEM);
    cudaFuncSetAttribute(fa_kernel, cudaFuncAttributeMaxDynamicSharedMemorySize, FA_SMEM);

    // 1: all weight packs in one launch
    pack_w_all<<<dim3(128, 128, 4), dim3(32, 8)>>>(wq, wk, wv, wo, wqkv, woT);

    // 2: pack activations
    {
        int n4 = S_LEN * D_MODEL / 4;
        pack_x_kernel<<<(n4 + 255) / 256, 256>>>(x, xp, D_MODEL);
    }

    // 3: fused QKV projection + rope + K-split + V^T packing epilogues
    mma_gemm<<<dim3(48, S_LEN / 128), 256, GEMM_SMEM>>>(
        xp, wqkv, nullptr, S_LEN, 6144, 4096, 1, fc, fs, qp, khl, vt);

    // 4: flash attention (tensor cores, LPT order)
    fa_kernel<<<dim3(S_LEN / 64, N_HEADS), 128, FA_SMEM>>>(qp, khl, vt, ap);

    // 5: output projection
    mma_gemm<<<dim3(4096 / 128, S_LEN / 128), 256, GEMM_SMEM>>>(
        ap, woT, out, S_LEN, 4096, 4096, 0, nullptr, nullptr, nullptr, nullptr, nullptr);
}